// round 1
// baseline (speedup 1.0000x reference)
#include <cuda_runtime.h>
#include <math.h>

#define B_ 32
#define S_ 1024
#define D_ 768
#define L_ 12

// ---------------- scratch (allocation-free rule: __device__ globals) ----------------
__device__ float g_h1[(size_t)B_ * S_ * D_];    // ping
__device__ float g_h2[(size_t)B_ * S_ * D_];    // pong
__device__ float g_Q [(size_t)B_ * S_ * D_];
__device__ float g_K [(size_t)B_ * S_ * D_];
__device__ float g_V [(size_t)B_ * S_ * D_];
__device__ float g_P [(size_t)B_ * S_ * S_];    // attention probs / scores

// ---------------- SGEMM: C = alpha*(A @ B[^T]) [+bias][*cscale] ----------------
// BT=false: B is (K,N) row-major (NN).  BT=true: B is (N,K) row-major (NT, C=A·Bᵀ).
// Tiles: BM=BN=128, BK=16, 256 threads, 8x8 per thread. Dims must be multiples.
template<bool BT>
__global__ __launch_bounds__(256)
void sgemm_kernel(const float* __restrict__ A, const float* __restrict__ Bm,
                  float* __restrict__ C,
                  int M, int N, int K, int lda, int ldb, int ldc,
                  long strideA, long strideB, long strideC,
                  const float* __restrict__ bias,
                  const float* __restrict__ cscale,
                  float alpha)
{
    constexpr int BM = 128, BN = 128, BK = 16;
    __shared__ float As[BK][BM];
    __shared__ float Bs[BK][BN];

    const int tid = threadIdx.x;
    const int z   = blockIdx.z;
    A  += (long)z * strideA;
    Bm += (long)z * strideB;
    C  += (long)z * strideC;

    const int tileM = blockIdx.y * BM;
    const int tileN = blockIdx.x * BN;

    const int tr = tid >> 4;   // 0..15
    const int tc = tid & 15;   // 0..15

    float acc[8][8];
    #pragma unroll
    for (int i = 0; i < 8; i++)
        #pragma unroll
        for (int j = 0; j < 8; j++) acc[i][j] = 0.f;

    // load indices for K-major tiles (A always; B when BT)
    const int arow = tid >> 2;          // 0..63
    const int acol = (tid & 3) << 2;    // 0,4,8,12
    // load indices for N-major tile (B when !BT)
    const int brow = tid >> 5;          // 0..7
    const int bcol = (tid & 31) << 2;   // 0..124

    for (int k0 = 0; k0 < K; k0 += BK) {
        // ---- load A tile (transposed into smem) ----
        #pragma unroll
        for (int p = 0; p < 2; p++) {
            const int r = arow + p * 64;
            const float4 v = *(const float4*)(A + (long)(tileM + r) * lda + k0 + acol);
            As[acol + 0][r] = v.x;
            As[acol + 1][r] = v.y;
            As[acol + 2][r] = v.z;
            As[acol + 3][r] = v.w;
        }
        // ---- load B tile ----
        if (BT) {
            #pragma unroll
            for (int p = 0; p < 2; p++) {
                const int r = arow + p * 64;
                const float4 v = *(const float4*)(Bm + (long)(tileN + r) * ldb + k0 + acol);
                Bs[acol + 0][r] = v.x;
                Bs[acol + 1][r] = v.y;
                Bs[acol + 2][r] = v.z;
                Bs[acol + 3][r] = v.w;
            }
        } else {
            #pragma unroll
            for (int p = 0; p < 2; p++) {
                const int r = brow + p * 8;
                *(float4*)&Bs[r][bcol] =
                    *(const float4*)(Bm + (long)(k0 + r) * ldb + tileN + bcol);
            }
        }
        __syncthreads();

        #pragma unroll
        for (int k = 0; k < BK; k++) {
            float rm[8], rn[8];
            *(float4*)(rm + 0) = *(const float4*)&As[k][tr * 8 + 0];
            *(float4*)(rm + 4) = *(const float4*)&As[k][tr * 8 + 4];
            *(float4*)(rn + 0) = *(const float4*)&Bs[k][tc * 8 + 0];
            *(float4*)(rn + 4) = *(const float4*)&Bs[k][tc * 8 + 4];
            #pragma unroll
            for (int i = 0; i < 8; i++)
                #pragma unroll
                for (int j = 0; j < 8; j++)
                    acc[i][j] = fmaf(rm[i], rn[j], acc[i][j]);
        }
        __syncthreads();
    }

    // ---- epilogue ----
    #pragma unroll
    for (int i = 0; i < 8; i++) {
        const long m = tileM + tr * 8 + i;
        #pragma unroll
        for (int j4 = 0; j4 < 2; j4++) {
            float4 r;
            float vals[4];
            #pragma unroll
            for (int t = 0; t < 4; t++) {
                const int n = tileN + tc * 8 + j4 * 4 + t;
                float v = acc[i][j4 * 4 + t] * alpha;
                if (bias)   v += bias[n];
                if (cscale) v *= cscale[n];
                vals[t] = v;
            }
            r.x = vals[0]; r.y = vals[1]; r.z = vals[2]; r.w = vals[3];
            *(float4*)(C + m * ldc + tileN + tc * 8 + j4 * 4) = r;
        }
    }
}

// ---------------- row softmax (in place), ncols = S_ ----------------
__global__ __launch_bounds__(256)
void softmax_rows_kernel(float* __restrict__ x, int ncols)
{
    const long row = blockIdx.x;
    float* p = x + row * (long)ncols;
    const int tid = threadIdx.x;
    __shared__ float red[8];

    float m = -1e30f;
    for (int c = tid; c < ncols; c += 256) m = fmaxf(m, p[c]);
    #pragma unroll
    for (int o = 16; o; o >>= 1) m = fmaxf(m, __shfl_xor_sync(0xFFFFFFFFu, m, o));
    if ((tid & 31) == 0) red[tid >> 5] = m;
    __syncthreads();
    if (tid < 8) {
        float t = red[tid];
        #pragma unroll
        for (int o = 4; o; o >>= 1) t = fmaxf(t, __shfl_xor_sync(0xFFu, t, o));
        if (tid == 0) red[0] = t;
    }
    __syncthreads();
    m = red[0];
    __syncthreads();

    float s = 0.f;
    for (int c = tid; c < ncols; c += 256) {
        float e = __expf(p[c] - m);
        p[c] = e;
        s += e;
    }
    #pragma unroll
    for (int o = 16; o; o >>= 1) s += __shfl_xor_sync(0xFFFFFFFFu, s, o);
    if ((tid & 31) == 0) red[tid >> 5] = s;
    __syncthreads();
    if (tid < 8) {
        float t = red[tid];
        #pragma unroll
        for (int o = 4; o; o >>= 1) t += __shfl_xor_sync(0xFFu, t, o);
        if (tid == 0) red[0] = t;
    }
    __syncthreads();
    const float inv = 1.f / red[0];
    for (int c = tid; c < ncols; c += 256) p[c] *= inv;
}

// ---------------- head: out[b] = h[b,0,:] . W_head + b_head ----------------
__global__ __launch_bounds__(256)
void head_kernel(const float* __restrict__ h, const float* __restrict__ Wh,
                 const float* __restrict__ bh, float* __restrict__ out)
{
    const int b = blockIdx.x;
    const float* p = h + (long)b * S_ * D_;
    const int tid = threadIdx.x;
    __shared__ float red[8];

    float s = 0.f;
    for (int d = tid; d < D_; d += 256) s += p[d] * Wh[d];
    #pragma unroll
    for (int o = 16; o; o >>= 1) s += __shfl_xor_sync(0xFFFFFFFFu, s, o);
    if ((tid & 31) == 0) red[tid >> 5] = s;
    __syncthreads();
    if (tid == 0) {
        float t = 0.f;
        #pragma unroll
        for (int w = 0; w < 8; w++) t += red[w];
        out[b] = t + bh[0];
    }
}

// ---------------- driver ----------------
extern "C" void kernel_launch(void* const* d_in, const int* in_sizes, int n_in,
                              void* d_out, int out_size)
{
    const float* hs     = (const float*)d_in[0];
    const float* Wq     = (const float*)d_in[1];
    const float* bq     = (const float*)d_in[2];
    const float* Wk     = (const float*)d_in[3];
    const float* bk     = (const float*)d_in[4];
    const float* Wv     = (const float*)d_in[5];
    const float* bv     = (const float*)d_in[6];
    const float* lk     = (const float*)d_in[7];
    const float* lv     = (const float*)d_in[8];
    const float* Whead  = (const float*)d_in[9];
    const float* bhead  = (const float*)d_in[10];
    float* out = (float*)d_out;

    float *h1, *h2, *Q, *K, *V, *P;
    cudaGetSymbolAddress((void**)&h1, g_h1);
    cudaGetSymbolAddress((void**)&h2, g_h2);
    cudaGetSymbolAddress((void**)&Q,  g_Q);
    cudaGetSymbolAddress((void**)&K,  g_K);
    cudaGetSymbolAddress((void**)&V,  g_V);
    cudaGetSymbolAddress((void**)&P,  g_P);

    const int M  = B_ * S_;            // 32768
    const float attn_alpha = 1.0f / sqrtf((float)D_);

    const dim3 blk(256);
    const dim3 grid_proj(D_ / 128, M / 128, 1);       // (6, 256, 1)
    const dim3 grid_qk(S_ / 128, S_ / 128, B_);       // (8, 8, 32)
    const dim3 grid_pv(D_ / 128, S_ / 128, B_);       // (6, 8, 32)

    const float* cur = hs;
    for (int l = 0; l < L_; l++) {
        const float* wq = Wq + (long)l * D_ * D_;
        const float* wk = Wk + (long)l * D_ * D_;
        const float* wv = Wv + (long)l * D_ * D_;
        const float* bq_i = bq + (long)l * D_;
        const float* bk_i = bk + (long)l * D_;
        const float* bv_i = bv + (long)l * D_;
        const float* lk_i = lk + (long)l * D_;
        const float* lv_i = lv + (long)l * D_;
        float* dst = (l & 1) ? h2 : h1;

        // Q = cur @ wq + bq
        sgemm_kernel<false><<<grid_proj, blk>>>(cur, wq, Q, M, D_, D_, D_, D_, D_,
                                                0, 0, 0, bq_i, nullptr, 1.0f);
        // K = (cur @ wk + bk) * lk
        sgemm_kernel<false><<<grid_proj, blk>>>(cur, wk, K, M, D_, D_, D_, D_, D_,
                                                0, 0, 0, bk_i, lk_i, 1.0f);
        // V = (cur @ wv + bv) * lv
        sgemm_kernel<false><<<grid_proj, blk>>>(cur, wv, V, M, D_, D_, D_, D_, D_,
                                                0, 0, 0, bv_i, lv_i, 1.0f);
        // P = alpha * Q @ K^T   (batched over B_)
        sgemm_kernel<true><<<grid_qk, blk>>>(Q, K, P, S_, S_, D_, D_, D_, S_,
                                             (long)S_ * D_, (long)S_ * D_, (long)S_ * S_,
                                             nullptr, nullptr, attn_alpha);
        // softmax rows
        softmax_rows_kernel<<<B_ * S_, blk>>>(P, S_);
        // dst = P @ V  (batched over B_)
        sgemm_kernel<false><<<grid_pv, blk>>>(P, V, dst, S_, D_, S_, S_, D_, D_,
                                              (long)S_ * S_, (long)S_ * D_, (long)S_ * D_,
                                              nullptr, nullptr, 1.0f);
        cur = dst;
    }

    head_kernel<<<B_, blk>>>(cur, Whead, bhead, out);
}

// round 3
// speedup vs baseline: 2.1636x; 2.1636x over previous
#include <cuda_runtime.h>
#include <cuda_bf16.h>
#include <math.h>
#include <stdint.h>

#define B_ 32
#define S_ 1024
#define D_ 768
#define L_ 12

// ===================== scratch (__device__ globals; no allocs) =====================
__device__ __align__(16) __nv_bfloat16 g_hh [(size_t)B_*S_*D_];
__device__ __align__(16) __nv_bfloat16 g_hl [(size_t)B_*S_*D_];
__device__ __align__(16) __nv_bfloat16 g_Qh [(size_t)B_*S_*D_];
__device__ __align__(16) __nv_bfloat16 g_Ql [(size_t)B_*S_*D_];
__device__ __align__(16) __nv_bfloat16 g_Kh [(size_t)B_*S_*D_];
__device__ __align__(16) __nv_bfloat16 g_Kl [(size_t)B_*S_*D_];
__device__ __align__(16) float         g_V  [(size_t)B_*S_*D_];
__device__ __align__(16) __nv_bfloat16 g_Vth[(size_t)B_*S_*D_];   // (B, D, S)
__device__ __align__(16) __nv_bfloat16 g_Vtl[(size_t)B_*S_*D_];
__device__ __align__(16) float         g_P  [(size_t)B_*S_*S_];
__device__ __align__(16) __nv_bfloat16 g_Ph [(size_t)B_*S_*S_];
__device__ __align__(16) __nv_bfloat16 g_Pl [(size_t)B_*S_*S_];
__device__ __align__(16) __nv_bfloat16 g_Wqth[(size_t)L_*D_*D_];
__device__ __align__(16) __nv_bfloat16 g_Wqtl[(size_t)L_*D_*D_];
__device__ __align__(16) __nv_bfloat16 g_Wkth[(size_t)L_*D_*D_];
__device__ __align__(16) __nv_bfloat16 g_Wktl[(size_t)L_*D_*D_];
__device__ __align__(16) __nv_bfloat16 g_Wvth[(size_t)L_*D_*D_];
__device__ __align__(16) __nv_bfloat16 g_Wvtl[(size_t)L_*D_*D_];

// ===================== PTX helpers (generic sm_80+ features only) =====================
__device__ __forceinline__ uint32_t smem_u32(const void* p) {
    uint32_t a;
    asm("{ .reg .u64 t; cvta.to.shared.u64 t, %1; cvt.u32.u64 %0, t; }" : "=r"(a) : "l"(p));
    return a;
}
__device__ __forceinline__ void cpa16(uint32_t s, const void* g) {
    asm volatile("cp.async.cg.shared.global [%0], [%1], 16;" :: "r"(s), "l"(g));
}
#define CP_COMMIT() asm volatile("cp.async.commit_group;" ::: "memory")
#define CP_WAIT1()  asm volatile("cp.async.wait_group 1;" ::: "memory")

__device__ __forceinline__ void ldm_x4(uint32_t& r0, uint32_t& r1, uint32_t& r2, uint32_t& r3,
                                       uint32_t a) {
    asm volatile("ldmatrix.sync.aligned.m8n8.x4.shared.b16 {%0,%1,%2,%3}, [%4];"
                 : "=r"(r0), "=r"(r1), "=r"(r2), "=r"(r3) : "r"(a));
}
__device__ __forceinline__ void mma_bf16(float* c, const uint32_t* a, const uint32_t* b) {
    asm volatile("mma.sync.aligned.m16n8k16.row.col.f32.bf16.bf16.f32 "
                 "{%0,%1,%2,%3}, {%4,%5,%6,%7}, {%8,%9}, {%0,%1,%2,%3};"
                 : "+f"(c[0]), "+f"(c[1]), "+f"(c[2]), "+f"(c[3])
                 : "r"(a[0]), "r"(a[1]), "r"(a[2]), "r"(a[3]), "r"(b[0]), "r"(b[1]));
}

// ===================== GEMM: C[M,N] = alpha * (A @ Bt^T) (+bias)(*csc) ==============
// A: [M,K] row-major split (Ah,Al).  Bt: [N,K] row-major split (Bh,Bl).
// bf16x3: acc += AhBh + AhBl + AlBh  (fp32 accum).
// OUT=0: fp32 C.  OUT=1: bf16 hi/lo split (Ch, Cl).
#define BM 128
#define BN 128
#define BKE 32                       // K elems per stage
#define ROWB 80                      // padded row bytes (32 bf16 = 64B + 16B pad)
#define TILEB (128 * ROWB)           // 10240 B per tile
#define STAGEB (4 * TILEB)           // Ah, Al, Bh, Bl
#define GEMM_SMEM (2 * STAGEB)       // 81920 B

template<int OUT>
__global__ __launch_bounds__(256, 1)
void gemm_mma(const __nv_bfloat16* __restrict__ Ah, const __nv_bfloat16* __restrict__ Al,
              const __nv_bfloat16* __restrict__ Bh, const __nv_bfloat16* __restrict__ Bl,
              float* __restrict__ Cf,
              __nv_bfloat16* __restrict__ Ch, __nv_bfloat16* __restrict__ Cl,
              const float* __restrict__ bias, const float* __restrict__ csc,
              float alpha, int K, int lda, int ldb, int ldc,
              long sA, long sB, long sC)
{
    extern __shared__ char smem[];
    const uint32_t sbase = smem_u32(smem);
    const int tid = threadIdx.x;
    const int lane = tid & 31, wid = tid >> 5;
    const int wm = wid & 3, wn = wid >> 2;          // 4 (M) x 2 (N) warps
    const int z = blockIdx.z;
    Ah += z * sA;  Al += z * sA;
    Bh += z * sB;  Bl += z * sB;

    const long tileM = blockIdx.y * (long)BM;
    const long tileN = blockIdx.x * (long)BN;

    // global load base pointers for this CTA
    const __nv_bfloat16* gAh = Ah + tileM * lda;
    const __nv_bfloat16* gAl = Al + tileM * lda;
    const __nv_bfloat16* gBh = Bh + tileN * ldb;
    const __nv_bfloat16* gBl = Bl + tileN * ldb;

    // per-thread load slots: q = it*256+tid -> row = q>>2, chunk = q&3 (16B each)
    const int r0q = tid >> 2, c0q = tid & 3;

    auto load_stage = [&](int stage, int k0) {
        const uint32_t sb = sbase + stage * STAGEB;
        #pragma unroll
        for (int it = 0; it < 2; it++) {
            const int r = r0q + it * 64;
            const long go = (long)r * lda + k0 + c0q * 8;
            const long gb = (long)r * ldb + k0 + c0q * 8;
            const uint32_t so = r * ROWB + c0q * 16;
            cpa16(sb + 0 * TILEB + so, gAh + go);
            cpa16(sb + 1 * TILEB + so, gAl + go);
            cpa16(sb + 2 * TILEB + so, gBh + gb);
            cpa16(sb + 3 * TILEB + so, gBl + gb);
        }
        CP_COMMIT();
    };

    float acc[2][8][4];
    #pragma unroll
    for (int i = 0; i < 2; i++)
        #pragma unroll
        for (int j = 0; j < 8; j++)
            #pragma unroll
            for (int q = 0; q < 4; q++) acc[i][j][q] = 0.f;

    const int nk = K / BKE;
    load_stage(0, 0);
    load_stage(1, BKE);

    // ldmatrix per-thread address components
    const int a_row  = wm * 32 + (lane & 15);                          // + ma*16
    const int b_row  = wn * 64 + (lane & 7) + ((lane >> 3) & 1) * 8;   // + nb*16
    const int colb   = (lane >> 4) * 16;                               // + ks*32

    for (int i = 0; i < nk; i++) {
        CP_WAIT1();
        __syncthreads();
        const uint32_t sb = sbase + (i & 1) * STAGEB;

        #pragma unroll
        for (int ks = 0; ks < 2; ks++) {
            uint32_t ah[2][4], al[2][4], bh[8][2], bl[8][2];
            #pragma unroll
            for (int ma = 0; ma < 2; ma++) {
                const uint32_t ad = sb + (a_row + ma * 16) * ROWB + ks * 32 + colb;
                ldm_x4(ah[ma][0], ah[ma][1], ah[ma][2], ah[ma][3], ad);
                ldm_x4(al[ma][0], al[ma][1], al[ma][2], al[ma][3], ad + TILEB);
            }
            #pragma unroll
            for (int nb = 0; nb < 4; nb++) {
                const uint32_t bd = sb + 2 * TILEB + (b_row + nb * 16) * ROWB + ks * 32 + colb;
                uint32_t t0, t1, t2, t3;
                ldm_x4(t0, t1, t2, t3, bd);
                bh[2*nb][0] = t0; bh[2*nb][1] = t2; bh[2*nb+1][0] = t1; bh[2*nb+1][1] = t3;
                ldm_x4(t0, t1, t2, t3, bd + TILEB);
                bl[2*nb][0] = t0; bl[2*nb][1] = t2; bl[2*nb+1][0] = t1; bl[2*nb+1][1] = t3;
            }
            // product-major ordering: 16 independent accs between dependent MMAs
            #pragma unroll
            for (int ma = 0; ma < 2; ma++)
                #pragma unroll
                for (int na = 0; na < 8; na++) mma_bf16(acc[ma][na], ah[ma], bh[na]);
            #pragma unroll
            for (int ma = 0; ma < 2; ma++)
                #pragma unroll
                for (int na = 0; na < 8; na++) mma_bf16(acc[ma][na], ah[ma], bl[na]);
            #pragma unroll
            for (int ma = 0; ma < 2; ma++)
                #pragma unroll
                for (int na = 0; na < 8; na++) mma_bf16(acc[ma][na], al[ma], bh[na]);
        }

        __syncthreads();
        if (i + 2 < nk) load_stage(i & 1, (i + 2) * BKE);
        else CP_COMMIT();   // keep group accounting uniform
    }

    // ===================== epilogue =====================
    const int gq = lane >> 2, rq = lane & 3;
    #pragma unroll
    for (int ma = 0; ma < 2; ma++) {
        #pragma unroll
        for (int half = 0; half < 2; half++) {
            const long row = tileM + wm * 32 + ma * 16 + gq + half * 8;
            #pragma unroll
            for (int na = 0; na < 8; na++) {
                const long col = tileN + wn * 64 + na * 8 + rq * 2;
                float v0 = acc[ma][na][half * 2 + 0] * alpha;
                float v1 = acc[ma][na][half * 2 + 1] * alpha;
                if (bias) { v0 += bias[col]; v1 += bias[col + 1]; }
                if (csc)  { v0 *= csc[col];  v1 *= csc[col + 1]; }
                if (OUT == 0) {
                    float2 f2; f2.x = v0; f2.y = v1;
                    *(float2*)(Cf + z * sC + row * ldc + col) = f2;
                } else {
                    const __nv_bfloat16 h0 = __float2bfloat16(v0);
                    const __nv_bfloat16 h1 = __float2bfloat16(v1);
                    const __nv_bfloat16 l0 = __float2bfloat16(v0 - __bfloat162float(h0));
                    const __nv_bfloat16 l1 = __float2bfloat16(v1 - __bfloat162float(h1));
                    __nv_bfloat162 hp; hp.x = h0; hp.y = h1;
                    __nv_bfloat162 lp; lp.x = l0; lp.y = l1;
                    *(__nv_bfloat162*)(Ch + z * sC + row * ldc + col) = hp;
                    *(__nv_bfloat162*)(Cl + z * sC + row * ldc + col) = lp;
                }
            }
        }
    }
}

// ===================== elementwise fp32 -> bf16 hi/lo split =====================
__global__ __launch_bounds__(256)
void split_kernel(const float* __restrict__ X, __nv_bfloat16* __restrict__ Xh,
                  __nv_bfloat16* __restrict__ Xl)
{
    const long i = ((long)blockIdx.x * 256 + threadIdx.x) * 4;
    const float4 f = *(const float4*)(X + i);
    float v[4] = {f.x, f.y, f.z, f.w};
    __nv_bfloat16 h[4], l[4];
    #pragma unroll
    for (int k = 0; k < 4; k++) {
        h[k] = __float2bfloat16(v[k]);
        l[k] = __float2bfloat16(v[k] - __bfloat162float(h[k]));
    }
    *(uint2*)(Xh + i) = *(const uint2*)h;
    *(uint2*)(Xl + i) = *(const uint2*)l;
}

// ===================== batched transpose + split: X(R,C) -> T(C,R) hi/lo =====================
__global__ void transpose_split(const float* __restrict__ X,
                                __nv_bfloat16* __restrict__ Th, __nv_bfloat16* __restrict__ Tl,
                                int R, int C, long sX, long sT)
{
    __shared__ float t[32][33];
    const int z = blockIdx.z;
    X  += z * sX;
    Th += z * sT;
    Tl += z * sT;
    const int c0 = blockIdx.x * 32, r0 = blockIdx.y * 32;
    const int tx = threadIdx.x, ty = threadIdx.y;
    #pragma unroll
    for (int k = 0; k < 4; k++)
        t[ty + 8*k][tx] = X[(long)(r0 + ty + 8*k) * C + c0 + tx];
    __syncthreads();
    #pragma unroll
    for (int k = 0; k < 4; k++) {
        const float v = t[tx][ty + 8*k];
        const long o = (long)(c0 + ty + 8*k) * R + r0 + tx;
        const __nv_bfloat16 h = __float2bfloat16(v);
        Th[o] = h;
        Tl[o] = __float2bfloat16(v - __bfloat162float(h));
    }
}

// ===================== row softmax: fp32 in -> bf16 hi/lo out =====================
__global__ __launch_bounds__(256)
void softmax_split(const float* __restrict__ P,
                   __nv_bfloat16* __restrict__ Ph, __nv_bfloat16* __restrict__ Pl)
{
    const long row = blockIdx.x;
    const int tid = threadIdx.x;
    __shared__ float red[8];

    const float4 f = *(const float4*)(P + row * S_ + tid * 4);
    float v[4] = {f.x, f.y, f.z, f.w};

    float m = fmaxf(fmaxf(v[0], v[1]), fmaxf(v[2], v[3]));
    #pragma unroll
    for (int o = 16; o; o >>= 1) m = fmaxf(m, __shfl_xor_sync(0xFFFFFFFFu, m, o));
    if ((tid & 31) == 0) red[tid >> 5] = m;
    __syncthreads();
    if (tid < 8) {
        float t = red[tid];
        #pragma unroll
        for (int o = 4; o; o >>= 1) t = fmaxf(t, __shfl_xor_sync(0xFFu, t, o));
        if (tid == 0) red[0] = t;
    }
    __syncthreads();
    m = red[0];
    __syncthreads();

    float s = 0.f;
    #pragma unroll
    for (int k = 0; k < 4; k++) { v[k] = __expf(v[k] - m); s += v[k]; }
    #pragma unroll
    for (int o = 16; o; o >>= 1) s += __shfl_xor_sync(0xFFFFFFFFu, s, o);
    if ((tid & 31) == 0) red[tid >> 5] = s;
    __syncthreads();
    if (tid < 8) {
        float t = red[tid];
        #pragma unroll
        for (int o = 4; o; o >>= 1) t += __shfl_xor_sync(0xFFu, t, o);
        if (tid == 0) red[0] = t;
    }
    __syncthreads();
    const float inv = 1.f / red[0];

    __nv_bfloat16 h[4], l[4];
    #pragma unroll
    for (int k = 0; k < 4; k++) {
        const float p = v[k] * inv;
        h[k] = __float2bfloat16(p);
        l[k] = __float2bfloat16(p - __bfloat162float(h[k]));
    }
    *(uint2*)(Ph + row * S_ + tid * 4) = *(const uint2*)h;
    *(uint2*)(Pl + row * S_ + tid * 4) = *(const uint2*)l;
}

// ===================== head: out[b] = (hh+hl)[b,0,:] . W_head + b_head =====================
__global__ __launch_bounds__(256)
void head_kernel(const __nv_bfloat16* __restrict__ hh, const __nv_bfloat16* __restrict__ hl,
                 const float* __restrict__ Wh, const float* __restrict__ bh,
                 float* __restrict__ out)
{
    const int b = blockIdx.x;
    const long base = (long)b * S_ * D_;
    const int tid = threadIdx.x;
    __shared__ float red[8];

    float s = 0.f;
    for (int d = tid; d < D_; d += 256)
        s += (__bfloat162float(hh[base + d]) + __bfloat162float(hl[base + d])) * Wh[d];
    #pragma unroll
    for (int o = 16; o; o >>= 1) s += __shfl_xor_sync(0xFFFFFFFFu, s, o);
    if ((tid & 31) == 0) red[tid >> 5] = s;
    __syncthreads();
    if (tid == 0) {
        float t = 0.f;
        #pragma unroll
        for (int w = 0; w < 8; w++) t += red[w];
        out[b] = t + bh[0];
    }
}

// ===================== driver =====================
extern "C" void kernel_launch(void* const* d_in, const int* in_sizes, int n_in,
                              void* d_out, int out_size)
{
    const float* hs    = (const float*)d_in[0];
    const float* Wq    = (const float*)d_in[1];
    const float* bq    = (const float*)d_in[2];
    const float* Wk    = (const float*)d_in[3];
    const float* bk    = (const float*)d_in[4];
    const float* Wv    = (const float*)d_in[5];
    const float* bv    = (const float*)d_in[6];
    const float* lk    = (const float*)d_in[7];
    const float* lv    = (const float*)d_in[8];
    const float* Whead = (const float*)d_in[9];
    const float* bhead = (const float*)d_in[10];
    float* out = (float*)d_out;

    __nv_bfloat16 *hh, *hl, *Qh, *Ql, *Kh, *Kl, *Vth, *Vtl, *Ph, *Pl;
    __nv_bfloat16 *Wqth, *Wqtl, *Wkth, *Wktl, *Wvth, *Wvtl;
    float *Vf, *P;
    cudaGetSymbolAddress((void**)&hh,  g_hh);   cudaGetSymbolAddress((void**)&hl,  g_hl);
    cudaGetSymbolAddress((void**)&Qh,  g_Qh);   cudaGetSymbolAddress((void**)&Ql,  g_Ql);
    cudaGetSymbolAddress((void**)&Kh,  g_Kh);   cudaGetSymbolAddress((void**)&Kl,  g_Kl);
    cudaGetSymbolAddress((void**)&Vf,  g_V);
    cudaGetSymbolAddress((void**)&Vth, g_Vth);  cudaGetSymbolAddress((void**)&Vtl, g_Vtl);
    cudaGetSymbolAddress((void**)&P,   g_P);
    cudaGetSymbolAddress((void**)&Ph,  g_Ph);   cudaGetSymbolAddress((void**)&Pl,  g_Pl);
    cudaGetSymbolAddress((void**)&Wqth, g_Wqth); cudaGetSymbolAddress((void**)&Wqtl, g_Wqtl);
    cudaGetSymbolAddress((void**)&Wkth, g_Wkth); cudaGetSymbolAddress((void**)&Wktl, g_Wktl);
    cudaGetSymbolAddress((void**)&Wvth, g_Wvth); cudaGetSymbolAddress((void**)&Wvtl, g_Wvtl);

    cudaFuncSetAttribute(gemm_mma<0>, cudaFuncAttributeMaxDynamicSharedMemorySize, GEMM_SMEM);
    cudaFuncSetAttribute(gemm_mma<1>, cudaFuncAttributeMaxDynamicSharedMemorySize, GEMM_SMEM);

    const float attn_alpha = 1.0f / sqrtf((float)D_);
    const long SD = (long)S_ * D_;
    const long SS = (long)S_ * S_;
    const long DD = (long)D_ * D_;

    // initial split of hidden states
    split_kernel<<<(B_ * S_ * D_) / (256 * 4), 256>>>(hs, hh, hl);

    // weights: (K,N) -> (N,K) transposed bf16 split, batched over layers
    {
        const dim3 tb(32, 8);
        const dim3 tg(D_ / 32, D_ / 32, L_);
        transpose_split<<<tg, tb>>>(Wq, Wqth, Wqtl, D_, D_, DD, DD);
        transpose_split<<<tg, tb>>>(Wk, Wkth, Wktl, D_, D_, DD, DD);
        transpose_split<<<tg, tb>>>(Wv, Wvth, Wvtl, D_, D_, DD, DD);
    }

    const dim3 blk(256);
    const dim3 grid_proj(D_ / BN, (B_ * S_) / BM, 1);   // (6, 256, 1)
    const dim3 grid_qk(S_ / BN, S_ / BM, B_);           // (8, 8, 32)
    const dim3 grid_pv(D_ / BN, S_ / BM, B_);           // (6, 8, 32)

    for (int l = 0; l < L_; l++) {
        const long wo = (long)l * DD;
        const float* bq_i = bq + (long)l * D_;
        const float* bk_i = bk + (long)l * D_;
        const float* bv_i = bv + (long)l * D_;
        const float* lk_i = lk + (long)l * D_;
        const float* lv_i = lv + (long)l * D_;

        // Q = h @ Wq + bq  -> split bf16
        gemm_mma<1><<<grid_proj, blk, GEMM_SMEM>>>(
            hh, hl, Wqth + wo, Wqtl + wo, nullptr, Qh, Ql,
            bq_i, nullptr, 1.0f, D_, D_, D_, D_, 0, 0, 0);
        // K = (h @ Wk + bk) * lk -> split bf16
        gemm_mma<1><<<grid_proj, blk, GEMM_SMEM>>>(
            hh, hl, Wkth + wo, Wktl + wo, nullptr, Kh, Kl,
            bk_i, lk_i, 1.0f, D_, D_, D_, D_, 0, 0, 0);
        // V = (h @ Wv + bv) * lv -> fp32
        gemm_mma<0><<<grid_proj, blk, GEMM_SMEM>>>(
            hh, hl, Wvth + wo, Wvtl + wo, Vf, nullptr, nullptr,
            bv_i, lv_i, 1.0f, D_, D_, D_, D_, 0, 0, 0);
        // V (B,S,D) -> Vt (B,D,S) split bf16
        {
            const dim3 tb(32, 8);
            const dim3 tg(D_ / 32, S_ / 32, B_);
            transpose_split<<<tg, tb>>>(Vf, Vth, Vtl, S_, D_, SD, SD);
        }
        // P = alpha * Q @ K^T -> fp32 (batched)
        gemm_mma<0><<<grid_qk, blk, GEMM_SMEM>>>(
            Qh, Ql, Kh, Kl, P, nullptr, nullptr,
            nullptr, nullptr, attn_alpha, D_, D_, D_, S_, SD, SD, SS);
        // softmax rows -> split bf16
        softmax_split<<<B_ * S_, blk>>>(P, Ph, Pl);
        // h = P @ V  (= P @ Vt^T) -> split bf16 (batched)
        gemm_mma<1><<<grid_pv, blk, GEMM_SMEM>>>(
            Ph, Pl, Vth, Vtl, nullptr, hh, hl,
            nullptr, nullptr, 1.0f, S_, S_, S_, D_, SS, SD, SD);
    }

    head_kernel<<<B_, blk>>>(hh, hl, Whead, bhead, out);
}

// round 4
// speedup vs baseline: 2.4206x; 1.1188x over previous
#include <cuda_runtime.h>
#include <cuda_bf16.h>
#include <math.h>
#include <stdint.h>

#define B_ 32
#define S_ 1024
#define D_ 768
#define L_ 12

// ===================== scratch (__device__ globals; no allocs) =====================
__device__ __align__(16) __nv_bfloat16 g_hh [(size_t)B_*S_*D_];
__device__ __align__(16) __nv_bfloat16 g_hl [(size_t)B_*S_*D_];
__device__ __align__(16) __nv_bfloat16 g_Qh [(size_t)B_*S_*D_];
__device__ __align__(16) __nv_bfloat16 g_Ql [(size_t)B_*S_*D_];
__device__ __align__(16) __nv_bfloat16 g_Kh [(size_t)B_*S_*D_];
__device__ __align__(16) __nv_bfloat16 g_Kl [(size_t)B_*S_*D_];
__device__ __align__(16) float         g_V  [(size_t)B_*S_*D_];
__device__ __align__(16) __nv_bfloat16 g_Vth[(size_t)B_*S_*D_];   // (B, D, S)
__device__ __align__(16) __nv_bfloat16 g_Vtl[(size_t)B_*S_*D_];
__device__ __align__(16) float         g_P  [(size_t)B_*S_*S_];
__device__ __align__(16) __nv_bfloat16 g_Ph [(size_t)B_*S_*S_];
__device__ __align__(16) __nv_bfloat16 g_Pl [(size_t)B_*S_*S_];
__device__ __align__(16) __nv_bfloat16 g_Wqth[(size_t)L_*D_*D_];
__device__ __align__(16) __nv_bfloat16 g_Wqtl[(size_t)L_*D_*D_];
__device__ __align__(16) __nv_bfloat16 g_Wkth[(size_t)L_*D_*D_];
__device__ __align__(16) __nv_bfloat16 g_Wktl[(size_t)L_*D_*D_];
__device__ __align__(16) __nv_bfloat16 g_Wvth[(size_t)L_*D_*D_];
__device__ __align__(16) __nv_bfloat16 g_Wvtl[(size_t)L_*D_*D_];

// ===================== PTX helpers (generic sm_80+ features only) =====================
__device__ __forceinline__ uint32_t smem_u32(const void* p) {
    uint32_t a;
    asm("{ .reg .u64 t; cvta.to.shared.u64 t, %1; cvt.u32.u64 %0, t; }" : "=r"(a) : "l"(p));
    return a;
}
__device__ __forceinline__ void cpa16(uint32_t s, const void* g) {
    asm volatile("cp.async.cg.shared.global [%0], [%1], 16;" :: "r"(s), "l"(g));
}
#define CP_COMMIT() asm volatile("cp.async.commit_group;" ::: "memory")
#define CP_WAIT1()  asm volatile("cp.async.wait_group 1;" ::: "memory")

__device__ __forceinline__ void ldm_x4(uint32_t& r0, uint32_t& r1, uint32_t& r2, uint32_t& r3,
                                       uint32_t a) {
    asm volatile("ldmatrix.sync.aligned.m8n8.x4.shared.b16 {%0,%1,%2,%3}, [%4];"
                 : "=r"(r0), "=r"(r1), "=r"(r2), "=r"(r3) : "r"(a));
}
__device__ __forceinline__ void mma_bf16(float* c, const uint32_t* a, const uint32_t* b) {
    asm volatile("mma.sync.aligned.m16n8k16.row.col.f32.bf16.bf16.f32 "
                 "{%0,%1,%2,%3}, {%4,%5,%6,%7}, {%8,%9}, {%0,%1,%2,%3};"
                 : "+f"(c[0]), "+f"(c[1]), "+f"(c[2]), "+f"(c[3])
                 : "r"(a[0]), "r"(a[1]), "r"(a[2]), "r"(a[3]), "r"(b[0]), "r"(b[1]));
}

// ===================== GEMM: C[M,N] = alpha * (A @ Bt^T) (+bias)(*csc) ==============
// A: [M,K] row-major split (Ah,Al).  Bt: [N,K] row-major split (Bh,Bl).
// bf16x3: acc += AhBh + AhBl + AlBh  (fp32 accum).
// OUT=0: fp32 C.  OUT=1: bf16 hi/lo split (Ch, Cl).
#define BM 128
#define BN 128
#define BKE 64                       // K elems per stage
#define ROWB 144                     // padded row bytes (64 bf16 = 128B + 16B pad)
#define TILEB (128 * ROWB)           // 18432 B per tile
#define STAGEB (4 * TILEB)           // Ah, Al, Bh, Bl = 73728 B
#define NSTG 3
#define GEMM_SMEM (NSTG * STAGEB)    // 221184 B

template<int OUT>
__global__ __launch_bounds__(256, 1)
void gemm_mma(const __nv_bfloat16* __restrict__ Ah, const __nv_bfloat16* __restrict__ Al,
              const __nv_bfloat16* __restrict__ Bh, const __nv_bfloat16* __restrict__ Bl,
              float* __restrict__ Cf,
              __nv_bfloat16* __restrict__ Ch, __nv_bfloat16* __restrict__ Cl,
              const float* __restrict__ bias, const float* __restrict__ csc,
              float alpha, int K, int lda, int ldb, int ldc,
              long sA, long sB, long sC)
{
    extern __shared__ char smem[];
    const uint32_t sbase = smem_u32(smem);
    const int tid = threadIdx.x;
    const int lane = tid & 31, wid = tid >> 5;
    const int wm = wid & 3, wn = wid >> 2;          // 4 (M) x 2 (N) warps
    const int z = blockIdx.z;
    Ah += z * sA;  Al += z * sA;
    Bh += z * sB;  Bl += z * sB;

    const long tileM = blockIdx.y * (long)BM;
    const long tileN = blockIdx.x * (long)BN;

    const __nv_bfloat16* gAh = Ah + tileM * lda;
    const __nv_bfloat16* gAl = Al + tileM * lda;
    const __nv_bfloat16* gBh = Bh + tileN * ldb;
    const __nv_bfloat16* gBl = Bl + tileN * ldb;

    // per-thread load slots: 128 rows x 8 chunks (16B) = 1024 slots, 4 per thread
    const int r0q = tid >> 3, c0q = tid & 7;

    auto load_stage = [&](int stage, int k0) {
        const uint32_t sb = sbase + stage * STAGEB;
        #pragma unroll
        for (int it = 0; it < 4; it++) {
            const int r = r0q + it * 32;
            const long go = (long)r * lda + k0 + c0q * 8;
            const long gb = (long)r * ldb + k0 + c0q * 8;
            const uint32_t so = r * ROWB + c0q * 16;
            cpa16(sb + 0 * TILEB + so, gAh + go);
            cpa16(sb + 1 * TILEB + so, gAl + go);
            cpa16(sb + 2 * TILEB + so, gBh + gb);
            cpa16(sb + 3 * TILEB + so, gBl + gb);
        }
        CP_COMMIT();
    };

    float acc[2][8][4];
    #pragma unroll
    for (int i = 0; i < 2; i++)
        #pragma unroll
        for (int j = 0; j < 8; j++)
            #pragma unroll
            for (int q = 0; q < 4; q++) acc[i][j][q] = 0.f;

    const int nk = K / BKE;
    load_stage(0, 0);
    load_stage(1, BKE);

    // ldmatrix per-thread address components
    const int a_row  = wm * 32 + (lane & 15);                          // + ma*16
    const int b_row  = wn * 64 + (lane & 7) + ((lane >> 3) & 1) * 8;   // + nb*16
    const int colb   = (lane >> 4) * 16;                               // + ks*32

    int buf = 0;
    for (int i = 0; i < nk; i++) {
        CP_WAIT1();            // stage i resident (commits so far: i+2, <=1 pending)
        __syncthreads();       // all warps done reading buf (i-1)%3 == (i+2)%3

        if (i + 2 < nk) {
            int nb2 = buf + 2; if (nb2 >= NSTG) nb2 -= NSTG;
            load_stage(nb2, (i + 2) * BKE);
        } else {
            CP_COMMIT();       // empty group keeps FIFO accounting uniform
        }

        const uint32_t sb = sbase + buf * STAGEB;

        #pragma unroll
        for (int ks = 0; ks < 4; ks++) {
            uint32_t ah[2][4], al[2][4], bh[8][2], bl[8][2];
            #pragma unroll
            for (int ma = 0; ma < 2; ma++) {
                const uint32_t ad = sb + (a_row + ma * 16) * ROWB + ks * 32 + colb;
                ldm_x4(ah[ma][0], ah[ma][1], ah[ma][2], ah[ma][3], ad);
                ldm_x4(al[ma][0], al[ma][1], al[ma][2], al[ma][3], ad + TILEB);
            }
            #pragma unroll
            for (int nb = 0; nb < 4; nb++) {
                const uint32_t bd = sb + 2 * TILEB + (b_row + nb * 16) * ROWB + ks * 32 + colb;
                uint32_t t0, t1, t2, t3;
                ldm_x4(t0, t1, t2, t3, bd);
                bh[2*nb][0] = t0; bh[2*nb][1] = t2; bh[2*nb+1][0] = t1; bh[2*nb+1][1] = t3;
                ldm_x4(t0, t1, t2, t3, bd + TILEB);
                bl[2*nb][0] = t0; bl[2*nb][1] = t2; bl[2*nb+1][0] = t1; bl[2*nb+1][1] = t3;
            }
            // product-major ordering: 16 independent accs between dependent MMAs
            #pragma unroll
            for (int ma = 0; ma < 2; ma++)
                #pragma unroll
                for (int na = 0; na < 8; na++) mma_bf16(acc[ma][na], ah[ma], bh[na]);
            #pragma unroll
            for (int ma = 0; ma < 2; ma++)
                #pragma unroll
                for (int na = 0; na < 8; na++) mma_bf16(acc[ma][na], ah[ma], bl[na]);
            #pragma unroll
            for (int ma = 0; ma < 2; ma++)
                #pragma unroll
                for (int na = 0; na < 8; na++) mma_bf16(acc[ma][na], al[ma], bh[na]);
        }

        if (++buf >= NSTG) buf = 0;
    }

    // ===================== epilogue =====================
    const int gq = lane >> 2, rq = lane & 3;
    #pragma unroll
    for (int ma = 0; ma < 2; ma++) {
        #pragma unroll
        for (int half = 0; half < 2; half++) {
            const long row = tileM + wm * 32 + ma * 16 + gq + half * 8;
            #pragma unroll
            for (int na = 0; na < 8; na++) {
                const long col = tileN + wn * 64 + na * 8 + rq * 2;
                float v0 = acc[ma][na][half * 2 + 0] * alpha;
                float v1 = acc[ma][na][half * 2 + 1] * alpha;
                if (bias) { v0 += bias[col]; v1 += bias[col + 1]; }
                if (csc)  { v0 *= csc[col];  v1 *= csc[col + 1]; }
                if (OUT == 0) {
                    float2 f2; f2.x = v0; f2.y = v1;
                    *(float2*)(Cf + z * sC + row * ldc + col) = f2;
                } else {
                    const __nv_bfloat16 h0 = __float2bfloat16(v0);
                    const __nv_bfloat16 h1 = __float2bfloat16(v1);
                    const __nv_bfloat16 l0 = __float2bfloat16(v0 - __bfloat162float(h0));
                    const __nv_bfloat16 l1 = __float2bfloat16(v1 - __bfloat162float(h1));
                    __nv_bfloat162 hp; hp.x = h0; hp.y = h1;
                    __nv_bfloat162 lp; lp.x = l0; lp.y = l1;
                    *(__nv_bfloat162*)(Ch + z * sC + row * ldc + col) = hp;
                    *(__nv_bfloat162*)(Cl + z * sC + row * ldc + col) = lp;
                }
            }
        }
    }
}

// ===================== elementwise fp32 -> bf16 hi/lo split =====================
__global__ __launch_bounds__(256)
void split_kernel(const float* __restrict__ X, __nv_bfloat16* __restrict__ Xh,
                  __nv_bfloat16* __restrict__ Xl)
{
    const long i = ((long)blockIdx.x * 256 + threadIdx.x) * 4;
    const float4 f = *(const float4*)(X + i);
    float v[4] = {f.x, f.y, f.z, f.w};
    __nv_bfloat16 h[4], l[4];
    #pragma unroll
    for (int k = 0; k < 4; k++) {
        h[k] = __float2bfloat16(v[k]);
        l[k] = __float2bfloat16(v[k] - __bfloat162float(h[k]));
    }
    *(uint2*)(Xh + i) = *(const uint2*)h;
    *(uint2*)(Xl + i) = *(const uint2*)l;
}

// ===================== batched transpose + split: X(R,C) -> T(C,R) hi/lo =====================
__global__ void transpose_split(const float* __restrict__ X,
                                __nv_bfloat16* __restrict__ Th, __nv_bfloat16* __restrict__ Tl,
                                int R, int C, long sX, long sT)
{
    __shared__ float t[32][33];
    const int z = blockIdx.z;
    X  += z * sX;
    Th += z * sT;
    Tl += z * sT;
    const int c0 = blockIdx.x * 32, r0 = blockIdx.y * 32;
    const int tx = threadIdx.x, ty = threadIdx.y;
    #pragma unroll
    for (int k = 0; k < 4; k++)
        t[ty + 8*k][tx] = X[(long)(r0 + ty + 8*k) * C + c0 + tx];
    __syncthreads();
    #pragma unroll
    for (int k = 0; k < 4; k++) {
        const float v = t[tx][ty + 8*k];
        const long o = (long)(c0 + ty + 8*k) * R + r0 + tx;
        const __nv_bfloat16 h = __float2bfloat16(v);
        Th[o] = h;
        Tl[o] = __float2bfloat16(v - __bfloat162float(h));
    }
}

// ===================== row softmax: fp32 in -> bf16 hi/lo out =====================
__global__ __launch_bounds__(256)
void softmax_split(const float* __restrict__ P,
                   __nv_bfloat16* __restrict__ Ph, __nv_bfloat16* __restrict__ Pl)
{
    const long row = blockIdx.x;
    const int tid = threadIdx.x;
    __shared__ float red[8];

    const float4 f = *(const float4*)(P + row * S_ + tid * 4);
    float v[4] = {f.x, f.y, f.z, f.w};

    float m = fmaxf(fmaxf(v[0], v[1]), fmaxf(v[2], v[3]));
    #pragma unroll
    for (int o = 16; o; o >>= 1) m = fmaxf(m, __shfl_xor_sync(0xFFFFFFFFu, m, o));
    if ((tid & 31) == 0) red[tid >> 5] = m;
    __syncthreads();
    if (tid < 8) {
        float t = red[tid];
        #pragma unroll
        for (int o = 4; o; o >>= 1) t = fmaxf(t, __shfl_xor_sync(0xFFu, t, o));
        if (tid == 0) red[0] = t;
    }
    __syncthreads();
    m = red[0];
    __syncthreads();

    float s = 0.f;
    #pragma unroll
    for (int k = 0; k < 4; k++) { v[k] = __expf(v[k] - m); s += v[k]; }
    #pragma unroll
    for (int o = 16; o; o >>= 1) s += __shfl_xor_sync(0xFFFFFFFFu, s, o);
    if ((tid & 31) == 0) red[tid >> 5] = s;
    __syncthreads();
    if (tid < 8) {
        float t = red[tid];
        #pragma unroll
        for (int o = 4; o; o >>= 1) t += __shfl_xor_sync(0xFFu, t, o);
        if (tid == 0) red[0] = t;
    }
    __syncthreads();
    const float inv = 1.f / red[0];

    __nv_bfloat16 h[4], l[4];
    #pragma unroll
    for (int k = 0; k < 4; k++) {
        const float p = v[k] * inv;
        h[k] = __float2bfloat16(p);
        l[k] = __float2bfloat16(p - __bfloat162float(h[k]));
    }
    *(uint2*)(Ph + row * S_ + tid * 4) = *(const uint2*)h;
    *(uint2*)(Pl + row * S_ + tid * 4) = *(const uint2*)l;
}

// ===================== head: out[b] = (hh+hl)[b,0,:] . W_head + b_head =====================
__global__ __launch_bounds__(256)
void head_kernel(const __nv_bfloat16* __restrict__ hh, const __nv_bfloat16* __restrict__ hl,
                 const float* __restrict__ Wh, const float* __restrict__ bh,
                 float* __restrict__ out)
{
    const int b = blockIdx.x;
    const long base = (long)b * S_ * D_;
    const int tid = threadIdx.x;
    __shared__ float red[8];

    float s = 0.f;
    for (int d = tid; d < D_; d += 256)
        s += (__bfloat162float(hh[base + d]) + __bfloat162float(hl[base + d])) * Wh[d];
    #pragma unroll
    for (int o = 16; o; o >>= 1) s += __shfl_xor_sync(0xFFFFFFFFu, s, o);
    if ((tid & 31) == 0) red[tid >> 5] = s;
    __syncthreads();
    if (tid == 0) {
        float t = 0.f;
        #pragma unroll
        for (int w = 0; w < 8; w++) t += red[w];
        out[b] = t + bh[0];
    }
}

// ===================== driver =====================
extern "C" void kernel_launch(void* const* d_in, const int* in_sizes, int n_in,
                              void* d_out, int out_size)
{
    const float* hs    = (const float*)d_in[0];
    const float* Wq    = (const float*)d_in[1];
    const float* bq    = (const float*)d_in[2];
    const float* Wk    = (const float*)d_in[3];
    const float* bk    = (const float*)d_in[4];
    const float* Wv    = (const float*)d_in[5];
    const float* bv    = (const float*)d_in[6];
    const float* lk    = (const float*)d_in[7];
    const float* lv    = (const float*)d_in[8];
    const float* Whead = (const float*)d_in[9];
    const float* bhead = (const float*)d_in[10];
    float* out = (float*)d_out;

    __nv_bfloat16 *hh, *hl, *Qh, *Ql, *Kh, *Kl, *Vth, *Vtl, *Ph, *Pl;
    __nv_bfloat16 *Wqth, *Wqtl, *Wkth, *Wktl, *Wvth, *Wvtl;
    float *Vf, *P;
    cudaGetSymbolAddress((void**)&hh,  g_hh);   cudaGetSymbolAddress((void**)&hl,  g_hl);
    cudaGetSymbolAddress((void**)&Qh,  g_Qh);   cudaGetSymbolAddress((void**)&Ql,  g_Ql);
    cudaGetSymbolAddress((void**)&Kh,  g_Kh);   cudaGetSymbolAddress((void**)&Kl,  g_Kl);
    cudaGetSymbolAddress((void**)&Vf,  g_V);
    cudaGetSymbolAddress((void**)&Vth, g_Vth);  cudaGetSymbolAddress((void**)&Vtl, g_Vtl);
    cudaGetSymbolAddress((void**)&P,   g_P);
    cudaGetSymbolAddress((void**)&Ph,  g_Ph);   cudaGetSymbolAddress((void**)&Pl,  g_Pl);
    cudaGetSymbolAddress((void**)&Wqth, g_Wqth); cudaGetSymbolAddress((void**)&Wqtl, g_Wqtl);
    cudaGetSymbolAddress((void**)&Wkth, g_Wkth); cudaGetSymbolAddress((void**)&Wktl, g_Wktl);
    cudaGetSymbolAddress((void**)&Wvth, g_Wvth); cudaGetSymbolAddress((void**)&Wvtl, g_Wvtl);

    cudaFuncSetAttribute(gemm_mma<0>, cudaFuncAttributeMaxDynamicSharedMemorySize, GEMM_SMEM);
    cudaFuncSetAttribute(gemm_mma<1>, cudaFuncAttributeMaxDynamicSharedMemorySize, GEMM_SMEM);

    const float attn_alpha = 1.0f / sqrtf((float)D_);
    const long SD = (long)S_ * D_;
    const long SS = (long)S_ * S_;
    const long DD = (long)D_ * D_;

    // initial split of hidden states
    split_kernel<<<(B_ * S_ * D_) / (256 * 4), 256>>>(hs, hh, hl);

    // weights: (K,N) -> (N,K) transposed bf16 split, batched over layers
    {
        const dim3 tb(32, 8);
        const dim3 tg(D_ / 32, D_ / 32, L_);
        transpose_split<<<tg, tb>>>(Wq, Wqth, Wqtl, D_, D_, DD, DD);
        transpose_split<<<tg, tb>>>(Wk, Wkth, Wktl, D_, D_, DD, DD);
        transpose_split<<<tg, tb>>>(Wv, Wvth, Wvtl, D_, D_, DD, DD);
    }

    const dim3 blk(256);
    const dim3 grid_proj(D_ / BN, (B_ * S_) / BM, 1);   // (6, 256, 1)
    const dim3 grid_qk(S_ / BN, S_ / BM, B_);           // (8, 8, 32)
    const dim3 grid_pv(D_ / BN, S_ / BM, B_);           // (6, 8, 32)

    for (int l = 0; l < L_; l++) {
        const long wo = (long)l * DD;
        const float* bq_i = bq + (long)l * D_;
        const float* bk_i = bk + (long)l * D_;
        const float* bv_i = bv + (long)l * D_;
        const float* lk_i = lk + (long)l * D_;
        const float* lv_i = lv + (long)l * D_;

        // Q = h @ Wq + bq  -> split bf16
        gemm_mma<1><<<grid_proj, blk, GEMM_SMEM>>>(
            hh, hl, Wqth + wo, Wqtl + wo, nullptr, Qh, Ql,
            bq_i, nullptr, 1.0f, D_, D_, D_, D_, 0, 0, 0);
        // K = (h @ Wk + bk) * lk -> split bf16
        gemm_mma<1><<<grid_proj, blk, GEMM_SMEM>>>(
            hh, hl, Wkth + wo, Wktl + wo, nullptr, Kh, Kl,
            bk_i, lk_i, 1.0f, D_, D_, D_, D_, 0, 0, 0);
        // V = (h @ Wv + bv) * lv -> fp32
        gemm_mma<0><<<grid_proj, blk, GEMM_SMEM>>>(
            hh, hl, Wvth + wo, Wvtl + wo, Vf, nullptr, nullptr,
            bv_i, lv_i, 1.0f, D_, D_, D_, D_, 0, 0, 0);
        // V (B,S,D) -> Vt (B,D,S) split bf16
        {
            const dim3 tb(32, 8);
            const dim3 tg(D_ / 32, S_ / 32, B_);
            transpose_split<<<tg, tb>>>(Vf, Vth, Vtl, S_, D_, SD, SD);
        }
        // P = alpha * Q @ K^T -> fp32 (batched)
        gemm_mma<0><<<grid_qk, blk, GEMM_SMEM>>>(
            Qh, Ql, Kh, Kl, P, nullptr, nullptr,
            nullptr, nullptr, attn_alpha, D_, D_, D_, S_, SD, SD, SS);
        // softmax rows -> split bf16
        softmax_split<<<B_ * S_, blk>>>(P, Ph, Pl);
        // h = P @ V  (= P @ Vt^T) -> split bf16 (batched)
        gemm_mma<1><<<grid_pv, blk, GEMM_SMEM>>>(
            Ph, Pl, Vth, Vtl, nullptr, hh, hl,
            nullptr, nullptr, 1.0f, S_, S_, S_, D_, SS, SD, SD);
    }

    head_kernel<<<B_, blk>>>(hh, hl, Whead, bhead, out);
}

// round 5
// speedup vs baseline: 2.4429x; 1.0092x over previous
#include <cuda_runtime.h>
#include <cuda_bf16.h>
#include <math.h>
#include <stdint.h>

#define B_ 32
#define S_ 1024
#define D_ 768
#define L_ 12

// ===================== scratch (__device__ globals; no allocs) =====================
__device__ __align__(16) __nv_bfloat16 g_hh [(size_t)B_*S_*D_];
__device__ __align__(16) __nv_bfloat16 g_hl [(size_t)B_*S_*D_];
__device__ __align__(16) __nv_bfloat16 g_Qh [(size_t)B_*S_*D_];
__device__ __align__(16) __nv_bfloat16 g_Ql [(size_t)B_*S_*D_];
__device__ __align__(16) __nv_bfloat16 g_Kh [(size_t)B_*S_*D_];
__device__ __align__(16) __nv_bfloat16 g_Kl [(size_t)B_*S_*D_];
__device__ __align__(16) float         g_V  [(size_t)B_*S_*D_];
__device__ __align__(16) __nv_bfloat16 g_Vth[(size_t)B_*S_*D_];   // (B, D, S)
__device__ __align__(16) __nv_bfloat16 g_Vtl[(size_t)B_*S_*D_];
__device__ __align__(16) float         g_P  [(size_t)B_*S_*S_];
__device__ __align__(16) __nv_bfloat16 g_Ph [(size_t)B_*S_*S_];
__device__ __align__(16) __nv_bfloat16 g_Pl [(size_t)B_*S_*S_];
__device__ __align__(16) __nv_bfloat16 g_Wqth[(size_t)L_*D_*D_];
__device__ __align__(16) __nv_bfloat16 g_Wqtl[(size_t)L_*D_*D_];
__device__ __align__(16) __nv_bfloat16 g_Wkth[(size_t)L_*D_*D_];
__device__ __align__(16) __nv_bfloat16 g_Wktl[(size_t)L_*D_*D_];
__device__ __align__(16) __nv_bfloat16 g_Wvth[(size_t)L_*D_*D_];
__device__ __align__(16) __nv_bfloat16 g_Wvtl[(size_t)L_*D_*D_];

// ===================== PTX helpers (generic sm_80+ features only) =====================
__device__ __forceinline__ uint32_t smem_u32(const void* p) {
    uint32_t a;
    asm("{ .reg .u64 t; cvta.to.shared.u64 t, %1; cvt.u32.u64 %0, t; }" : "=r"(a) : "l"(p));
    return a;
}
__device__ __forceinline__ void cpa16(uint32_t s, const void* g) {
    asm volatile("cp.async.cg.shared.global [%0], [%1], 16;" :: "r"(s), "l"(g));
}
#define CP_COMMIT() asm volatile("cp.async.commit_group;" ::: "memory")
#define CP_WAIT1()  asm volatile("cp.async.wait_group 1;" ::: "memory")

__device__ __forceinline__ void ldm_x4(uint32_t& r0, uint32_t& r1, uint32_t& r2, uint32_t& r3,
                                       uint32_t a) {
    asm volatile("ldmatrix.sync.aligned.m8n8.x4.shared.b16 {%0,%1,%2,%3}, [%4];"
                 : "=r"(r0), "=r"(r1), "=r"(r2), "=r"(r3) : "r"(a));
}
__device__ __forceinline__ void mma_bf16(float* c, const uint32_t* a, const uint32_t* b) {
    asm volatile("mma.sync.aligned.m16n8k16.row.col.f32.bf16.bf16.f32 "
                 "{%0,%1,%2,%3}, {%4,%5,%6,%7}, {%8,%9}, {%0,%1,%2,%3};"
                 : "+f"(c[0]), "+f"(c[1]), "+f"(c[2]), "+f"(c[3])
                 : "r"(a[0]), "r"(a[1]), "r"(a[2]), "r"(a[3]), "r"(b[0]), "r"(b[1]));
}

// ===================== GEMM: C[M,N] = alpha * (A @ Bt^T) (+bias)(*csc) ==============
// A: [M,K] row-major split (Ah,Al).  Bt: [N,K] row-major split (Bh,Bl).
// bf16x3: acc += AhBh + AhBl + AlBh  (fp32 accum).
// OUT=0: fp32 C.  OUT=1: bf16 hi/lo split (Ch, Cl).
// 2 CTAs/SM: smem 81920/CTA, regs capped at 128.
#define BM 128
#define BN 128
#define BKE 32                       // K elems per stage
#define ROWB 80                      // padded row bytes (32 bf16 = 64B + 16B pad)
#define TILEB (128 * ROWB)           // 10240 B per tile
#define STAGEB (4 * TILEB)           // Ah, Al, Bh, Bl = 40960 B
#define GEMM_SMEM (2 * STAGEB)       // 81920 B

template<int OUT>
__global__ __launch_bounds__(256, 2)
void gemm_mma(const __nv_bfloat16* __restrict__ Ah, const __nv_bfloat16* __restrict__ Al,
              const __nv_bfloat16* __restrict__ Bh, const __nv_bfloat16* __restrict__ Bl,
              float* __restrict__ Cf,
              __nv_bfloat16* __restrict__ Ch, __nv_bfloat16* __restrict__ Cl,
              const float* __restrict__ bias, const float* __restrict__ csc,
              float alpha, int K, int lda, int ldb, int ldc,
              long sA, long sB, long sC)
{
    extern __shared__ char smem[];
    const uint32_t sbase = smem_u32(smem);
    const int tid = threadIdx.x;
    const int lane = tid & 31, wid = tid >> 5;
    const int wm = wid & 3, wn = wid >> 2;          // 4 (M) x 2 (N) warps
    const int z = blockIdx.z;
    Ah += z * sA;  Al += z * sA;
    Bh += z * sB;  Bl += z * sB;

    const long tileM = blockIdx.y * (long)BM;
    const long tileN = blockIdx.x * (long)BN;

    const __nv_bfloat16* gAh = Ah + tileM * lda;
    const __nv_bfloat16* gAl = Al + tileM * lda;
    const __nv_bfloat16* gBh = Bh + tileN * ldb;
    const __nv_bfloat16* gBl = Bl + tileN * ldb;

    // per-thread load slots: 128 rows x 4 chunks (16B) = 512 slots, 2 per thread
    const int r0q = tid >> 2, c0q = tid & 3;

    auto load_stage = [&](int stage, int k0) {
        const uint32_t sb = sbase + stage * STAGEB;
        #pragma unroll
        for (int it = 0; it < 2; it++) {
            const int r = r0q + it * 64;
            const long go = (long)r * lda + k0 + c0q * 8;
            const long gb = (long)r * ldb + k0 + c0q * 8;
            const uint32_t so = r * ROWB + c0q * 16;
            cpa16(sb + 0 * TILEB + so, gAh + go);
            cpa16(sb + 1 * TILEB + so, gAl + go);
            cpa16(sb + 2 * TILEB + so, gBh + gb);
            cpa16(sb + 3 * TILEB + so, gBl + gb);
        }
        CP_COMMIT();
    };

    float acc[2][8][4];
    #pragma unroll
    for (int i = 0; i < 2; i++)
        #pragma unroll
        for (int j = 0; j < 8; j++)
            #pragma unroll
            for (int q = 0; q < 4; q++) acc[i][j][q] = 0.f;

    const int nk = K / BKE;
    load_stage(0, 0);
    load_stage(1, BKE);

    // ldmatrix per-thread address components
    const int a_row  = wm * 32 + (lane & 15);                          // + ma*16
    const int b_row  = wn * 64 + (lane & 7) + ((lane >> 3) & 1) * 8;   // + nb*16
    const int colb   = (lane >> 4) * 16;                               // + ks*32

    for (int i = 0; i < nk; i++) {
        CP_WAIT1();
        __syncthreads();
        const uint32_t sb = sbase + (i & 1) * STAGEB;

        #pragma unroll
        for (int ks = 0; ks < 2; ks++) {
            uint32_t ah[2][4], al[2][4], bh[8][2], bl[8][2];
            #pragma unroll
            for (int ma = 0; ma < 2; ma++) {
                const uint32_t ad = sb + (a_row + ma * 16) * ROWB + ks * 32 + colb;
                ldm_x4(ah[ma][0], ah[ma][1], ah[ma][2], ah[ma][3], ad);
                ldm_x4(al[ma][0], al[ma][1], al[ma][2], al[ma][3], ad + TILEB);
            }
            #pragma unroll
            for (int nb = 0; nb < 4; nb++) {
                const uint32_t bd = sb + 2 * TILEB + (b_row + nb * 16) * ROWB + ks * 32 + colb;
                uint32_t t0, t1, t2, t3;
                ldm_x4(t0, t1, t2, t3, bd);
                bh[2*nb][0] = t0; bh[2*nb][1] = t2; bh[2*nb+1][0] = t1; bh[2*nb+1][1] = t3;
                ldm_x4(t0, t1, t2, t3, bd + TILEB);
                bl[2*nb][0] = t0; bl[2*nb][1] = t2; bl[2*nb+1][0] = t1; bl[2*nb+1][1] = t3;
            }
            // product-major ordering: 16 independent accs between dependent MMAs
            #pragma unroll
            for (int ma = 0; ma < 2; ma++)
                #pragma unroll
                for (int na = 0; na < 8; na++) mma_bf16(acc[ma][na], ah[ma], bh[na]);
            #pragma unroll
            for (int ma = 0; ma < 2; ma++)
                #pragma unroll
                for (int na = 0; na < 8; na++) mma_bf16(acc[ma][na], ah[ma], bl[na]);
            #pragma unroll
            for (int ma = 0; ma < 2; ma++)
                #pragma unroll
                for (int na = 0; na < 8; na++) mma_bf16(acc[ma][na], al[ma], bh[na]);
        }

        __syncthreads();
        if (i + 2 < nk) load_stage(i & 1, (i + 2) * BKE);
        else CP_COMMIT();   // keep group accounting uniform
    }

    // ===================== epilogue =====================
    const int gq = lane >> 2, rq = lane & 3;
    #pragma unroll
    for (int ma = 0; ma < 2; ma++) {
        #pragma unroll
        for (int half = 0; half < 2; half++) {
            const long row = tileM + wm * 32 + ma * 16 + gq + half * 8;
            #pragma unroll
            for (int na = 0; na < 8; na++) {
                const long col = tileN + wn * 64 + na * 8 + rq * 2;
                float v0 = acc[ma][na][half * 2 + 0] * alpha;
                float v1 = acc[ma][na][half * 2 + 1] * alpha;
                if (bias) { v0 += bias[col]; v1 += bias[col + 1]; }
                if (csc)  { v0 *= csc[col];  v1 *= csc[col + 1]; }
                if (OUT == 0) {
                    float2 f2; f2.x = v0; f2.y = v1;
                    *(float2*)(Cf + z * sC + row * ldc + col) = f2;
                } else {
                    const __nv_bfloat16 h0 = __float2bfloat16(v0);
                    const __nv_bfloat16 h1 = __float2bfloat16(v1);
                    const __nv_bfloat16 l0 = __float2bfloat16(v0 - __bfloat162float(h0));
                    const __nv_bfloat16 l1 = __float2bfloat16(v1 - __bfloat162float(h1));
                    __nv_bfloat162 hp; hp.x = h0; hp.y = h1;
                    __nv_bfloat162 lp; lp.x = l0; lp.y = l1;
                    *(__nv_bfloat162*)(Ch + z * sC + row * ldc + col) = hp;
                    *(__nv_bfloat162*)(Cl + z * sC + row * ldc + col) = lp;
                }
            }
        }
    }
}

// ===================== elementwise fp32 -> bf16 hi/lo split =====================
__global__ __launch_bounds__(256)
void split_kernel(const float* __restrict__ X, __nv_bfloat16* __restrict__ Xh,
                  __nv_bfloat16* __restrict__ Xl)
{
    const long i = ((long)blockIdx.x * 256 + threadIdx.x) * 4;
    const float4 f = *(const float4*)(X + i);
    float v[4] = {f.x, f.y, f.z, f.w};
    __nv_bfloat16 h[4], l[4];
    #pragma unroll
    for (int k = 0; k < 4; k++) {
        h[k] = __float2bfloat16(v[k]);
        l[k] = __float2bfloat16(v[k] - __bfloat162float(h[k]));
    }
    *(uint2*)(Xh + i) = *(const uint2*)h;
    *(uint2*)(Xl + i) = *(const uint2*)l;
}

// ===================== batched transpose + split: X(R,C) -> T(C,R) hi/lo =====================
__global__ void transpose_split(const float* __restrict__ X,
                                __nv_bfloat16* __restrict__ Th, __nv_bfloat16* __restrict__ Tl,
                                int R, int C, long sX, long sT)
{
    __shared__ float t[32][33];
    const int z = blockIdx.z;
    X  += z * sX;
    Th += z * sT;
    Tl += z * sT;
    const int c0 = blockIdx.x * 32, r0 = blockIdx.y * 32;
    const int tx = threadIdx.x, ty = threadIdx.y;
    #pragma unroll
    for (int k = 0; k < 4; k++)
        t[ty + 8*k][tx] = X[(long)(r0 + ty + 8*k) * C + c0 + tx];
    __syncthreads();
    #pragma unroll
    for (int k = 0; k < 4; k++) {
        const float v = t[tx][ty + 8*k];
        const long o = (long)(c0 + ty + 8*k) * R + r0 + tx;
        const __nv_bfloat16 h = __float2bfloat16(v);
        Th[o] = h;
        Tl[o] = __float2bfloat16(v - __bfloat162float(h));
    }
}

// ===================== row softmax: fp32 in -> bf16 hi/lo out =====================
__global__ __launch_bounds__(256)
void softmax_split(const float* __restrict__ P,
                   __nv_bfloat16* __restrict__ Ph, __nv_bfloat16* __restrict__ Pl)
{
    const long row = blockIdx.x;
    const int tid = threadIdx.x;
    __shared__ float red[8];

    const float4 f = *(const float4*)(P + row * S_ + tid * 4);
    float v[4] = {f.x, f.y, f.z, f.w};

    float m = fmaxf(fmaxf(v[0], v[1]), fmaxf(v[2], v[3]));
    #pragma unroll
    for (int o = 16; o; o >>= 1) m = fmaxf(m, __shfl_xor_sync(0xFFFFFFFFu, m, o));
    if ((tid & 31) == 0) red[tid >> 5] = m;
    __syncthreads();
    if (tid < 8) {
        float t = red[tid];
        #pragma unroll
        for (int o = 4; o; o >>= 1) t = fmaxf(t, __shfl_xor_sync(0xFFu, t, o));
        if (tid == 0) red[0] = t;
    }
    __syncthreads();
    m = red[0];
    __syncthreads();

    float s = 0.f;
    #pragma unroll
    for (int k = 0; k < 4; k++) { v[k] = __expf(v[k] - m); s += v[k]; }
    #pragma unroll
    for (int o = 16; o; o >>= 1) s += __shfl_xor_sync(0xFFFFFFFFu, s, o);
    if ((tid & 31) == 0) red[tid >> 5] = s;
    __syncthreads();
    if (tid < 8) {
        float t = red[tid];
        #pragma unroll
        for (int o = 4; o; o >>= 1) t += __shfl_xor_sync(0xFFu, t, o);
        if (tid == 0) red[0] = t;
    }
    __syncthreads();
    const float inv = 1.f / red[0];

    __nv_bfloat16 h[4], l[4];
    #pragma unroll
    for (int k = 0; k < 4; k++) {
        const float p = v[k] * inv;
        h[k] = __float2bfloat16(p);
        l[k] = __float2bfloat16(p - __bfloat162float(h[k]));
    }
    *(uint2*)(Ph + row * S_ + tid * 4) = *(const uint2*)h;
    *(uint2*)(Pl + row * S_ + tid * 4) = *(const uint2*)l;
}

// ===================== head: out[b] = (hh+hl)[b,0,:] . W_head + b_head =====================
__global__ __launch_bounds__(256)
void head_kernel(const __nv_bfloat16* __restrict__ hh, const __nv_bfloat16* __restrict__ hl,
                 const float* __restrict__ Wh, const float* __restrict__ bh,
                 float* __restrict__ out)
{
    const int b = blockIdx.x;
    const long base = (long)b * S_ * D_;
    const int tid = threadIdx.x;
    __shared__ float red[8];

    float s = 0.f;
    for (int d = tid; d < D_; d += 256)
        s += (__bfloat162float(hh[base + d]) + __bfloat162float(hl[base + d])) * Wh[d];
    #pragma unroll
    for (int o = 16; o; o >>= 1) s += __shfl_xor_sync(0xFFFFFFFFu, s, o);
    if ((tid & 31) == 0) red[tid >> 5] = s;
    __syncthreads();
    if (tid == 0) {
        float t = 0.f;
        #pragma unroll
        for (int w = 0; w < 8; w++) t += red[w];
        out[b] = t + bh[0];
    }
}

// ===================== driver =====================
extern "C" void kernel_launch(void* const* d_in, const int* in_sizes, int n_in,
                              void* d_out, int out_size)
{
    const float* hs    = (const float*)d_in[0];
    const float* Wq    = (const float*)d_in[1];
    const float* bq    = (const float*)d_in[2];
    const float* Wk    = (const float*)d_in[3];
    const float* bk    = (const float*)d_in[4];
    const float* Wv    = (const float*)d_in[5];
    const float* bv    = (const float*)d_in[6];
    const float* lk    = (const float*)d_in[7];
    const float* lv    = (const float*)d_in[8];
    const float* Whead = (const float*)d_in[9];
    const float* bhead = (const float*)d_in[10];
    float* out = (float*)d_out;

    __nv_bfloat16 *hh, *hl, *Qh, *Ql, *Kh, *Kl, *Vth, *Vtl, *Ph, *Pl;
    __nv_bfloat16 *Wqth, *Wqtl, *Wkth, *Wktl, *Wvth, *Wvtl;
    float *Vf, *P;
    cudaGetSymbolAddress((void**)&hh,  g_hh);   cudaGetSymbolAddress((void**)&hl,  g_hl);
    cudaGetSymbolAddress((void**)&Qh,  g_Qh);   cudaGetSymbolAddress((void**)&Ql,  g_Ql);
    cudaGetSymbolAddress((void**)&Kh,  g_Kh);   cudaGetSymbolAddress((void**)&Kl,  g_Kl);
    cudaGetSymbolAddress((void**)&Vf,  g_V);
    cudaGetSymbolAddress((void**)&Vth, g_Vth);  cudaGetSymbolAddress((void**)&Vtl, g_Vtl);
    cudaGetSymbolAddress((void**)&P,   g_P);
    cudaGetSymbolAddress((void**)&Ph,  g_Ph);   cudaGetSymbolAddress((void**)&Pl,  g_Pl);
    cudaGetSymbolAddress((void**)&Wqth, g_Wqth); cudaGetSymbolAddress((void**)&Wqtl, g_Wqtl);
    cudaGetSymbolAddress((void**)&Wkth, g_Wkth); cudaGetSymbolAddress((void**)&Wktl, g_Wktl);
    cudaGetSymbolAddress((void**)&Wvth, g_Wvth); cudaGetSymbolAddress((void**)&Wvtl, g_Wvtl);

    cudaFuncSetAttribute(gemm_mma<0>, cudaFuncAttributeMaxDynamicSharedMemorySize, GEMM_SMEM);
    cudaFuncSetAttribute(gemm_mma<1>, cudaFuncAttributeMaxDynamicSharedMemorySize, GEMM_SMEM);

    const float attn_alpha = 1.0f / sqrtf((float)D_);
    const long SD = (long)S_ * D_;
    const long SS = (long)S_ * S_;
    const long DD = (long)D_ * D_;

    // initial split of hidden states
    split_kernel<<<(B_ * S_ * D_) / (256 * 4), 256>>>(hs, hh, hl);

    // weights: (K,N) -> (N,K) transposed bf16 split, batched over layers
    {
        const dim3 tb(32, 8);
        const dim3 tg(D_ / 32, D_ / 32, L_);
        transpose_split<<<tg, tb>>>(Wq, Wqth, Wqtl, D_, D_, DD, DD);
        transpose_split<<<tg, tb>>>(Wk, Wkth, Wktl, D_, D_, DD, DD);
        transpose_split<<<tg, tb>>>(Wv, Wvth, Wvtl, D_, D_, DD, DD);
    }

    const dim3 blk(256);
    const dim3 grid_proj(D_ / BN, (B_ * S_) / BM, 1);   // (6, 256, 1)
    const dim3 grid_qk(S_ / BN, S_ / BM, B_);           // (8, 8, 32)
    const dim3 grid_pv(D_ / BN, S_ / BM, B_);           // (6, 8, 32)

    for (int l = 0; l < L_; l++) {
        const long wo = (long)l * DD;
        const float* bq_i = bq + (long)l * D_;
        const float* bk_i = bk + (long)l * D_;
        const float* bv_i = bv + (long)l * D_;
        const float* lk_i = lk + (long)l * D_;
        const float* lv_i = lv + (long)l * D_;

        // Q = h @ Wq + bq  -> split bf16
        gemm_mma<1><<<grid_proj, blk, GEMM_SMEM>>>(
            hh, hl, Wqth + wo, Wqtl + wo, nullptr, Qh, Ql,
            bq_i, nullptr, 1.0f, D_, D_, D_, D_, 0, 0, 0);
        // K = (h @ Wk + bk) * lk -> split bf16
        gemm_mma<1><<<grid_proj, blk, GEMM_SMEM>>>(
            hh, hl, Wkth + wo, Wktl + wo, nullptr, Kh, Kl,
            bk_i, lk_i, 1.0f, D_, D_, D_, D_, 0, 0, 0);
        // V = (h @ Wv + bv) * lv -> fp32
        gemm_mma<0><<<grid_proj, blk, GEMM_SMEM>>>(
            hh, hl, Wvth + wo, Wvtl + wo, Vf, nullptr, nullptr,
            bv_i, lv_i, 1.0f, D_, D_, D_, D_, 0, 0, 0);
        // V (B,S,D) -> Vt (B,D,S) split bf16
        {
            const dim3 tb(32, 8);
            const dim3 tg(D_ / 32, S_ / 32, B_);
            transpose_split<<<tg, tb>>>(Vf, Vth, Vtl, S_, D_, SD, SD);
        }
        // P = alpha * Q @ K^T -> fp32 (batched)
        gemm_mma<0><<<grid_qk, blk, GEMM_SMEM>>>(
            Qh, Ql, Kh, Kl, P, nullptr, nullptr,
            nullptr, nullptr, attn_alpha, D_, D_, D_, S_, SD, SD, SS);
        // softmax rows -> split bf16
        softmax_split<<<B_ * S_, blk>>>(P, Ph, Pl);
        // h = P @ V  (= P @ Vt^T) -> split bf16 (batched)
        gemm_mma<1><<<grid_pv, blk, GEMM_SMEM>>>(
            Ph, Pl, Vth, Vtl, nullptr, hh, hl,
            nullptr, nullptr, 1.0f, S_, S_, S_, D_, SS, SD, SD);
    }

    head_kernel<<<B_, blk>>>(hh, hl, Whead, bhead, out);
}

// round 6
// speedup vs baseline: 2.4445x; 1.0007x over previous
#include <cuda_runtime.h>
#include <cuda_bf16.h>
#include <math.h>
#include <stdint.h>

#define B_ 32
#define S_ 1024
#define D_ 768
#define L_ 12

// ===================== scratch (__device__ globals; no allocs) =====================
__device__ __align__(16) __nv_bfloat16 g_hh [(size_t)B_*S_*D_];
__device__ __align__(16) __nv_bfloat16 g_hl [(size_t)B_*S_*D_];
__device__ __align__(16) __nv_bfloat16 g_Qh [(size_t)B_*S_*D_];
__device__ __align__(16) __nv_bfloat16 g_Ql [(size_t)B_*S_*D_];
__device__ __align__(16) __nv_bfloat16 g_Kh [(size_t)B_*S_*D_];
__device__ __align__(16) __nv_bfloat16 g_Kl [(size_t)B_*S_*D_];
__device__ __align__(16) float         g_V  [(size_t)B_*S_*D_];
__device__ __align__(16) __nv_bfloat16 g_Vth[(size_t)B_*S_*D_];   // (B, D, S)
__device__ __align__(16) __nv_bfloat16 g_Vtl[(size_t)B_*S_*D_];
__device__ __align__(16) float         g_P  [(size_t)B_*S_*S_];
__device__ __align__(16) __nv_bfloat16 g_Ph [(size_t)B_*S_*S_];
__device__ __align__(16) __nv_bfloat16 g_Pl [(size_t)B_*S_*S_];
__device__ __align__(16) __nv_bfloat16 g_Wqth[(size_t)L_*D_*D_];
__device__ __align__(16) __nv_bfloat16 g_Wqtl[(size_t)L_*D_*D_];
__device__ __align__(16) __nv_bfloat16 g_Wkth[(size_t)L_*D_*D_];
__device__ __align__(16) __nv_bfloat16 g_Wktl[(size_t)L_*D_*D_];
__device__ __align__(16) __nv_bfloat16 g_Wvth[(size_t)L_*D_*D_];
__device__ __align__(16) __nv_bfloat16 g_Wvtl[(size_t)L_*D_*D_];

// ===================== PTX helpers (generic sm_80+ features only) =====================
__device__ __forceinline__ uint32_t smem_u32(const void* p) {
    uint32_t a;
    asm("{ .reg .u64 t; cvta.to.shared.u64 t, %1; cvt.u32.u64 %0, t; }" : "=r"(a) : "l"(p));
    return a;
}
__device__ __forceinline__ void cpa16(uint32_t s, const void* g) {
    asm volatile("cp.async.cg.shared.global [%0], [%1], 16;" :: "r"(s), "l"(g));
}
#define CP_COMMIT() asm volatile("cp.async.commit_group;" ::: "memory")
#define CP_WAIT1()  asm volatile("cp.async.wait_group 1;" ::: "memory")

__device__ __forceinline__ void ldm_x4(uint32_t& r0, uint32_t& r1, uint32_t& r2, uint32_t& r3,
                                       uint32_t a) {
    asm volatile("ldmatrix.sync.aligned.m8n8.x4.shared.b16 {%0,%1,%2,%3}, [%4];"
                 : "=r"(r0), "=r"(r1), "=r"(r2), "=r"(r3) : "r"(a));
}
__device__ __forceinline__ void mma_bf16(float* c, const uint32_t* a, const uint32_t* b) {
    asm volatile("mma.sync.aligned.m16n8k16.row.col.f32.bf16.bf16.f32 "
                 "{%0,%1,%2,%3}, {%4,%5,%6,%7}, {%8,%9}, {%0,%1,%2,%3};"
                 : "+f"(c[0]), "+f"(c[1]), "+f"(c[2]), "+f"(c[3])
                 : "r"(a[0]), "r"(a[1]), "r"(a[2]), "r"(a[3]), "r"(b[0]), "r"(b[1]));
}

// ===================== GEMM: C[M,N] = alpha * (A @ Bt^T) (+bias)(*csc) ==============
// A: [M,K] row-major split (Ah,Al).  Bt: [N,K] row-major split (Bh,Bl).
// bf16x3: acc += AhBh + AhBl + AlBh  (fp32 accum).
// OUT=0: fp32 C.  OUT=1: bf16 hi/lo split (Ch, Cl).
// 2 CTAs/SM: smem 81920/CTA, regs capped at 128.
#define BM 128
#define BN 128
#define BKE 32                       // K elems per stage
#define ROWB 80                      // padded row bytes (32 bf16 = 64B + 16B pad)
#define TILEB (128 * ROWB)           // 10240 B per tile
#define STAGEB (4 * TILEB)           // Ah, Al, Bh, Bl = 40960 B
#define GEMM_SMEM (2 * STAGEB)       // 81920 B

template<int OUT>
__global__ __launch_bounds__(256, 2)
void gemm_mma(const __nv_bfloat16* __restrict__ Ah, const __nv_bfloat16* __restrict__ Al,
              const __nv_bfloat16* __restrict__ Bh, const __nv_bfloat16* __restrict__ Bl,
              float* __restrict__ Cf,
              __nv_bfloat16* __restrict__ Ch, __nv_bfloat16* __restrict__ Cl,
              const float* __restrict__ bias, const float* __restrict__ csc,
              float alpha, int K, int lda, int ldb, int ldc,
              long sA, long sB, long sC)
{
    extern __shared__ char smem[];
    const uint32_t sbase = smem_u32(smem);
    const int tid = threadIdx.x;
    const int lane = tid & 31, wid = tid >> 5;
    const int wm = wid & 3, wn = wid >> 2;          // 4 (M) x 2 (N) warps
    const int z = blockIdx.z;
    Ah += z * sA;  Al += z * sA;
    Bh += z * sB;  Bl += z * sB;

    const long tileM = blockIdx.y * (long)BM;
    const long tileN = blockIdx.x * (long)BN;

    const __nv_bfloat16* gAh = Ah + tileM * lda;
    const __nv_bfloat16* gAl = Al + tileM * lda;
    const __nv_bfloat16* gBh = Bh + tileN * ldb;
    const __nv_bfloat16* gBl = Bl + tileN * ldb;

    // per-thread load slots: 128 rows x 4 chunks (16B) = 512 slots, 2 per thread
    const int r0q = tid >> 2, c0q = tid & 3;

    auto load_stage = [&](int stage, int k0) {
        const uint32_t sb = sbase + stage * STAGEB;
        #pragma unroll
        for (int it = 0; it < 2; it++) {
            const int r = r0q + it * 64;
            const long go = (long)r * lda + k0 + c0q * 8;
            const long gb = (long)r * ldb + k0 + c0q * 8;
            const uint32_t so = r * ROWB + c0q * 16;
            cpa16(sb + 0 * TILEB + so, gAh + go);
            cpa16(sb + 1 * TILEB + so, gAl + go);
            cpa16(sb + 2 * TILEB + so, gBh + gb);
            cpa16(sb + 3 * TILEB + so, gBl + gb);
        }
        CP_COMMIT();
    };

    float acc[2][8][4];
    #pragma unroll
    for (int i = 0; i < 2; i++)
        #pragma unroll
        for (int j = 0; j < 8; j++)
            #pragma unroll
            for (int q = 0; q < 4; q++) acc[i][j][q] = 0.f;

    const int nk = K / BKE;
    load_stage(0, 0);
    load_stage(1, BKE);

    // ldmatrix per-thread address components
    const int a_row  = wm * 32 + (lane & 15);                          // + ma*16
    const int b_row  = wn * 64 + (lane & 7) + ((lane >> 3) & 1) * 8;   // + nb*16
    const int colb   = (lane >> 4) * 16;                               // + ks*32

    for (int i = 0; i < nk; i++) {
        CP_WAIT1();
        __syncthreads();
        const uint32_t sb = sbase + (i & 1) * STAGEB;

        #pragma unroll
        for (int ks = 0; ks < 2; ks++) {
            uint32_t ah[2][4], al[2][4], bh[8][2], bl[8][2];
            #pragma unroll
            for (int ma = 0; ma < 2; ma++) {
                const uint32_t ad = sb + (a_row + ma * 16) * ROWB + ks * 32 + colb;
                ldm_x4(ah[ma][0], ah[ma][1], ah[ma][2], ah[ma][3], ad);
                ldm_x4(al[ma][0], al[ma][1], al[ma][2], al[ma][3], ad + TILEB);
            }
            #pragma unroll
            for (int nb = 0; nb < 4; nb++) {
                const uint32_t bd = sb + 2 * TILEB + (b_row + nb * 16) * ROWB + ks * 32 + colb;
                uint32_t t0, t1, t2, t3;
                ldm_x4(t0, t1, t2, t3, bd);
                bh[2*nb][0] = t0; bh[2*nb][1] = t2; bh[2*nb+1][0] = t1; bh[2*nb+1][1] = t3;
                ldm_x4(t0, t1, t2, t3, bd + TILEB);
                bl[2*nb][0] = t0; bl[2*nb][1] = t2; bl[2*nb+1][0] = t1; bl[2*nb+1][1] = t3;
            }
            // product-major ordering: 16 independent accs between dependent MMAs
            #pragma unroll
            for (int ma = 0; ma < 2; ma++)
                #pragma unroll
                for (int na = 0; na < 8; na++) mma_bf16(acc[ma][na], ah[ma], bh[na]);
            #pragma unroll
            for (int ma = 0; ma < 2; ma++)
                #pragma unroll
                for (int na = 0; na < 8; na++) mma_bf16(acc[ma][na], ah[ma], bl[na]);
            #pragma unroll
            for (int ma = 0; ma < 2; ma++)
                #pragma unroll
                for (int na = 0; na < 8; na++) mma_bf16(acc[ma][na], al[ma], bh[na]);
        }

        __syncthreads();
        if (i + 2 < nk) load_stage(i & 1, (i + 2) * BKE);
        else CP_COMMIT();   // keep group accounting uniform
    }

    // ===================== epilogue =====================
    const int gq = lane >> 2, rq = lane & 3;
    #pragma unroll
    for (int ma = 0; ma < 2; ma++) {
        #pragma unroll
        for (int half = 0; half < 2; half++) {
            const long row = tileM + wm * 32 + ma * 16 + gq + half * 8;
            #pragma unroll
            for (int na = 0; na < 8; na++) {
                const long col = tileN + wn * 64 + na * 8 + rq * 2;
                float v0 = acc[ma][na][half * 2 + 0] * alpha;
                float v1 = acc[ma][na][half * 2 + 1] * alpha;
                if (bias) { v0 += bias[col]; v1 += bias[col + 1]; }
                if (csc)  { v0 *= csc[col];  v1 *= csc[col + 1]; }
                if (OUT == 0) {
                    float2 f2; f2.x = v0; f2.y = v1;
                    *(float2*)(Cf + z * sC + row * ldc + col) = f2;
                } else {
                    const __nv_bfloat16 h0 = __float2bfloat16(v0);
                    const __nv_bfloat16 h1 = __float2bfloat16(v1);
                    const __nv_bfloat16 l0 = __float2bfloat16(v0 - __bfloat162float(h0));
                    const __nv_bfloat16 l1 = __float2bfloat16(v1 - __bfloat162float(h1));
                    __nv_bfloat162 hp; hp.x = h0; hp.y = h1;
                    __nv_bfloat162 lp; lp.x = l0; lp.y = l1;
                    *(__nv_bfloat162*)(Ch + z * sC + row * ldc + col) = hp;
                    *(__nv_bfloat162*)(Cl + z * sC + row * ldc + col) = lp;
                }
            }
        }
    }
}

// ===================== elementwise fp32 -> bf16 hi/lo split =====================
__global__ __launch_bounds__(256)
void split_kernel(const float* __restrict__ X, __nv_bfloat16* __restrict__ Xh,
                  __nv_bfloat16* __restrict__ Xl)
{
    const long i = ((long)blockIdx.x * 256 + threadIdx.x) * 4;
    const float4 f = *(const float4*)(X + i);
    float v[4] = {f.x, f.y, f.z, f.w};
    __nv_bfloat16 h[4], l[4];
    #pragma unroll
    for (int k = 0; k < 4; k++) {
        h[k] = __float2bfloat16(v[k]);
        l[k] = __float2bfloat16(v[k] - __bfloat162float(h[k]));
    }
    *(uint2*)(Xh + i) = *(const uint2*)h;
    *(uint2*)(Xl + i) = *(const uint2*)l;
}

// ===================== batched transpose + split: X(R,C) -> T(C,R) hi/lo =====================
__global__ void transpose_split(const float* __restrict__ X,
                                __nv_bfloat16* __restrict__ Th, __nv_bfloat16* __restrict__ Tl,
                                int R, int C, long sX, long sT)
{
    __shared__ float t[32][33];
    const int z = blockIdx.z;
    X  += z * sX;
    Th += z * sT;
    Tl += z * sT;
    const int c0 = blockIdx.x * 32, r0 = blockIdx.y * 32;
    const int tx = threadIdx.x, ty = threadIdx.y;
    #pragma unroll
    for (int k = 0; k < 4; k++)
        t[ty + 8*k][tx] = X[(long)(r0 + ty + 8*k) * C + c0 + tx];
    __syncthreads();
    #pragma unroll
    for (int k = 0; k < 4; k++) {
        const float v = t[tx][ty + 8*k];
        const long o = (long)(c0 + ty + 8*k) * R + r0 + tx;
        const __nv_bfloat16 h = __float2bfloat16(v);
        Th[o] = h;
        Tl[o] = __float2bfloat16(v - __bfloat162float(h));
    }
}

// ===================== row softmax: fp32 in -> bf16 hi/lo out =====================
__global__ __launch_bounds__(256)
void softmax_split(const float* __restrict__ P,
                   __nv_bfloat16* __restrict__ Ph, __nv_bfloat16* __restrict__ Pl)
{
    const long row = blockIdx.x;
    const int tid = threadIdx.x;
    __shared__ float red[8];

    const float4 f = *(const float4*)(P + row * S_ + tid * 4);
    float v[4] = {f.x, f.y, f.z, f.w};

    float m = fmaxf(fmaxf(v[0], v[1]), fmaxf(v[2], v[3]));
    #pragma unroll
    for (int o = 16; o; o >>= 1) m = fmaxf(m, __shfl_xor_sync(0xFFFFFFFFu, m, o));
    if ((tid & 31) == 0) red[tid >> 5] = m;
    __syncthreads();
    if (tid < 8) {
        float t = red[tid];
        #pragma unroll
        for (int o = 4; o; o >>= 1) t = fmaxf(t, __shfl_xor_sync(0xFFu, t, o));
        if (tid == 0) red[0] = t;
    }
    __syncthreads();
    m = red[0];
    __syncthreads();

    float s = 0.f;
    #pragma unroll
    for (int k = 0; k < 4; k++) { v[k] = __expf(v[k] - m); s += v[k]; }
    #pragma unroll
    for (int o = 16; o; o >>= 1) s += __shfl_xor_sync(0xFFFFFFFFu, s, o);
    if ((tid & 31) == 0) red[tid >> 5] = s;
    __syncthreads();
    if (tid < 8) {
        float t = red[tid];
        #pragma unroll
        for (int o = 4; o; o >>= 1) t += __shfl_xor_sync(0xFFu, t, o);
        if (tid == 0) red[0] = t;
    }
    __syncthreads();
    const float inv = 1.f / red[0];

    __nv_bfloat16 h[4], l[4];
    #pragma unroll
    for (int k = 0; k < 4; k++) {
        const float p = v[k] * inv;
        h[k] = __float2bfloat16(p);
        l[k] = __float2bfloat16(p - __bfloat162float(h[k]));
    }
    *(uint2*)(Ph + row * S_ + tid * 4) = *(const uint2*)h;
    *(uint2*)(Pl + row * S_ + tid * 4) = *(const uint2*)l;
}

// ===================== head: out[b] = (hh+hl)[b,0,:] . W_head + b_head =====================
__global__ __launch_bounds__(256)
void head_kernel(const __nv_bfloat16* __restrict__ hh, const __nv_bfloat16* __restrict__ hl,
                 const float* __restrict__ Wh, const float* __restrict__ bh,
                 float* __restrict__ out)
{
    const int b = blockIdx.x;
    const long base = (long)b * S_ * D_;
    const int tid = threadIdx.x;
    __shared__ float red[8];

    float s = 0.f;
    for (int d = tid; d < D_; d += 256)
        s += (__bfloat162float(hh[base + d]) + __bfloat162float(hl[base + d])) * Wh[d];
    #pragma unroll
    for (int o = 16; o; o >>= 1) s += __shfl_xor_sync(0xFFFFFFFFu, s, o);
    if ((tid & 31) == 0) red[tid >> 5] = s;
    __syncthreads();
    if (tid == 0) {
        float t = 0.f;
        #pragma unroll
        for (int w = 0; w < 8; w++) t += red[w];
        out[b] = t + bh[0];
    }
}

// ===================== driver =====================
extern "C" void kernel_launch(void* const* d_in, const int* in_sizes, int n_in,
                              void* d_out, int out_size)
{
    const float* hs    = (const float*)d_in[0];
    const float* Wq    = (const float*)d_in[1];
    const float* bq    = (const float*)d_in[2];
    const float* Wk    = (const float*)d_in[3];
    const float* bk    = (const float*)d_in[4];
    const float* Wv    = (const float*)d_in[5];
    const float* bv    = (const float*)d_in[6];
    const float* lk    = (const float*)d_in[7];
    const float* lv    = (const float*)d_in[8];
    const float* Whead = (const float*)d_in[9];
    const float* bhead = (const float*)d_in[10];
    float* out = (float*)d_out;

    __nv_bfloat16 *hh, *hl, *Qh, *Ql, *Kh, *Kl, *Vth, *Vtl, *Ph, *Pl;
    __nv_bfloat16 *Wqth, *Wqtl, *Wkth, *Wktl, *Wvth, *Wvtl;
    float *Vf, *P;
    cudaGetSymbolAddress((void**)&hh,  g_hh);   cudaGetSymbolAddress((void**)&hl,  g_hl);
    cudaGetSymbolAddress((void**)&Qh,  g_Qh);   cudaGetSymbolAddress((void**)&Ql,  g_Ql);
    cudaGetSymbolAddress((void**)&Kh,  g_Kh);   cudaGetSymbolAddress((void**)&Kl,  g_Kl);
    cudaGetSymbolAddress((void**)&Vf,  g_V);
    cudaGetSymbolAddress((void**)&Vth, g_Vth);  cudaGetSymbolAddress((void**)&Vtl, g_Vtl);
    cudaGetSymbolAddress((void**)&P,   g_P);
    cudaGetSymbolAddress((void**)&Ph,  g_Ph);   cudaGetSymbolAddress((void**)&Pl,  g_Pl);
    cudaGetSymbolAddress((void**)&Wqth, g_Wqth); cudaGetSymbolAddress((void**)&Wqtl, g_Wqtl);
    cudaGetSymbolAddress((void**)&Wkth, g_Wkth); cudaGetSymbolAddress((void**)&Wktl, g_Wktl);
    cudaGetSymbolAddress((void**)&Wvth, g_Wvth); cudaGetSymbolAddress((void**)&Wvtl, g_Wvtl);

    cudaFuncSetAttribute(gemm_mma<0>, cudaFuncAttributeMaxDynamicSharedMemorySize, GEMM_SMEM);
    cudaFuncSetAttribute(gemm_mma<1>, cudaFuncAttributeMaxDynamicSharedMemorySize, GEMM_SMEM);

    const float attn_alpha = 1.0f / sqrtf((float)D_);
    const long SD = (long)S_ * D_;
    const long SS = (long)S_ * S_;
    const long DD = (long)D_ * D_;

    // initial split of hidden states
    split_kernel<<<(B_ * S_ * D_) / (256 * 4), 256>>>(hs, hh, hl);

    // weights: (K,N) -> (N,K) transposed bf16 split, batched over layers
    {
        const dim3 tb(32, 8);
        const dim3 tg(D_ / 32, D_ / 32, L_);
        transpose_split<<<tg, tb>>>(Wq, Wqth, Wqtl, D_, D_, DD, DD);
        transpose_split<<<tg, tb>>>(Wk, Wkth, Wktl, D_, D_, DD, DD);
        transpose_split<<<tg, tb>>>(Wv, Wvth, Wvtl, D_, D_, DD, DD);
    }

    const dim3 blk(256);
    const dim3 grid_proj(D_ / BN, (B_ * S_) / BM, 1);   // (6, 256, 1)
    const dim3 grid_qk(S_ / BN, S_ / BM, B_);           // (8, 8, 32)
    const dim3 grid_pv(D_ / BN, S_ / BM, B_);           // (6, 8, 32)

    for (int l = 0; l < L_; l++) {
        const long wo = (long)l * DD;
        const float* bq_i = bq + (long)l * D_;
        const float* bk_i = bk + (long)l * D_;
        const float* bv_i = bv + (long)l * D_;
        const float* lk_i = lk + (long)l * D_;
        const float* lv_i = lv + (long)l * D_;

        // Q = h @ Wq + bq  -> split bf16
        gemm_mma<1><<<grid_proj, blk, GEMM_SMEM>>>(
            hh, hl, Wqth + wo, Wqtl + wo, nullptr, Qh, Ql,
            bq_i, nullptr, 1.0f, D_, D_, D_, D_, 0, 0, 0);
        // K = (h @ Wk + bk) * lk -> split bf16
        gemm_mma<1><<<grid_proj, blk, GEMM_SMEM>>>(
            hh, hl, Wkth + wo, Wktl + wo, nullptr, Kh, Kl,
            bk_i, lk_i, 1.0f, D_, D_, D_, D_, 0, 0, 0);
        // V = (h @ Wv + bv) * lv -> fp32
        gemm_mma<0><<<grid_proj, blk, GEMM_SMEM>>>(
            hh, hl, Wvth + wo, Wvtl + wo, Vf, nullptr, nullptr,
            bv_i, lv_i, 1.0f, D_, D_, D_, D_, 0, 0, 0);
        // V (B,S,D) -> Vt (B,D,S) split bf16
        {
            const dim3 tb(32, 8);
            const dim3 tg(D_ / 32, S_ / 32, B_);
            transpose_split<<<tg, tb>>>(Vf, Vth, Vtl, S_, D_, SD, SD);
        }
        // P = alpha * Q @ K^T -> fp32 (batched)
        gemm_mma<0><<<grid_qk, blk, GEMM_SMEM>>>(
            Qh, Ql, Kh, Kl, P, nullptr, nullptr,
            nullptr, nullptr, attn_alpha, D_, D_, D_, S_, SD, SD, SS);
        // softmax rows -> split bf16
        softmax_split<<<B_ * S_, blk>>>(P, Ph, Pl);
        // h = P @ V  (= P @ Vt^T) -> split bf16 (batched)
        gemm_mma<1><<<grid_pv, blk, GEMM_SMEM>>>(
            Ph, Pl, Vth, Vtl, nullptr, hh, hl,
            nullptr, nullptr, 1.0f, S_, S_, S_, D_, SS, SD, SD);
    }

    head_kernel<<<B_, blk>>>(hh, hl, Whead, bhead, out);
}